// round 4
// baseline (speedup 1.0000x reference)
#include <cuda_runtime.h>

#define DIM   192
#define TDIM  576
#define WSZ   8
#define PIX   64
#define IMG   256
#define SHIFTV 4
#define NTHR  512

// smem layout (floats)
#define XS_OFF 0
#define QS_OFF 12288
#define KS_OFF 24576
#define VS_OFF 36864
#define AS_OFF 49152
#define NS_OFF 55296
#define SMEM_FLOATS 55680 // 222720 bytes

typedef unsigned long long ull;

// Packed weights: P[(s*32+rg)][c][6] — each (s,rg) block is 192*6 floats
// contiguous; a c-pair (12 floats) = 3 x 16B aligned loads.
__device__ float g_qkvP[96 * 1152];
__device__ float g_projP[32 * 1152];

__global__ void wtrans_kernel(const float* __restrict__ qkv_w,
                              const float* __restrict__ proj_w) {
    int i = blockIdx.x * 256 + threadIdx.x;
    if (i < 96 * 1152) {
        int b = i / 1152, rem = i % 1152;
        int c = rem / 6, r = rem % 6;
        int s = b >> 5, rg = b & 31;
        int o = s * 192 + rg * 6 + r;
        g_qkvP[i] = qkv_w[o * 192 + c];
    }
    if (i < 32 * 1152) {
        int b = i / 1152, rem = i % 1152;
        int c = rem / 6, r = rem % 6;
        int o = b * 6 + r;
        g_projP[i] = proj_w[o * 192 + c];
    }
}

__device__ __forceinline__ ull dup2(float v) {
    ull r;
    asm("mov.b64 %0, {%1, %1};" : "=l"(r) : "f"(v));
    return r;
}
__device__ __forceinline__ void ffma2(ull& d, ull a, ull b) {
    asm("fma.rn.f32x2 %0, %1, %2, %0;" : "+l"(d) : "l"(a), "l"(b));
}
__device__ __forceinline__ float2 ull2f2(ull v) {
    float2 r;
    asm("mov.b64 {%0, %1}, %2;" : "=f"(r.x), "=f"(r.y) : "l"(v));
    return r;
}

__global__ void __launch_bounds__(NTHR, 1)
attn_kernel(const float* __restrict__ x, const float* __restrict__ dw_w,
            const float* __restrict__ temperature, float* __restrict__ out) {
    extern __shared__ float sm[];
    float* Xs = sm + XS_OFF;
    float* Qs = sm + QS_OFF;
    float* Ks = sm + KS_OFF;
    float* Vs = sm + VS_OFF;
    float* As = sm + AS_OFF;
    float* Ns = sm + NS_OFF;

    const int tid = threadIdx.x;
    const int win = blockIdx.x;
    const int bi = win >> 10;
    const int wh = (win >> 5) & 31;
    const int ww = win & 31;
    const int rg = tid >> 4;   // 32 groups of 6 rows
    const int cg = tid & 15;   // 16 float4 columns
    const int lane = tid & 31;
    const int wid = tid >> 5;

    // ---- load window with roll(-4, -4) ----
    {
        const float* xb = x + (size_t)bi * DIM * IMG * IMG;
        for (int e = tid; e < DIM * PIX; e += NTHR) {
            int c = e >> 6, p = e & 63;
            int i = p >> 3, j = p & 7;
            int gh = (wh * WSZ + i + SHIFTV) & 255;
            int gw = (ww * WSZ + j + SHIFTV) & 255;
            Xs[e] = xb[(c * IMG + gh) * IMG + gw];
        }
    }
    __syncthreads();

    // ---- fused qkv GEMM, c processed in pairs, weights via 3xLDG.128 ----
    {
        ull acc[3][3][4];
#pragma unroll
        for (int s = 0; s < 3; s++)
#pragma unroll
            for (int p = 0; p < 3; p++)
#pragma unroll
                for (int j = 0; j < 4; j++) acc[s][p][j] = 0ull;
        const float4* s4 = (const float4*)Xs;
        const ulonglong2* wp0 = (const ulonglong2*)(g_qkvP + (size_t)(0 * 32 + rg) * 1152);
        const ulonglong2* wp1 = (const ulonglong2*)(g_qkvP + (size_t)(1 * 32 + rg) * 1152);
        const ulonglong2* wp2 = (const ulonglong2*)(g_qkvP + (size_t)(2 * 32 + rg) * 1152);
#pragma unroll 2
        for (int cc = 0; cc < 96; cc++) {
            float4 xa = s4[(2 * cc) * 16 + cg];
            float4 xb = s4[(2 * cc + 1) * 16 + cg];
            ull a0 = dup2(xa.x), a1 = dup2(xa.y), a2 = dup2(xa.z), a3 = dup2(xa.w);
            ull b0 = dup2(xb.x), b1 = dup2(xb.y), b2 = dup2(xb.z), b3 = dup2(xb.w);
            const ulonglong2* wps[3] = {wp0 + cc * 3, wp1 + cc * 3, wp2 + cc * 3};
#pragma unroll
            for (int s = 0; s < 3; s++) {
                ulonglong2 u0 = __ldg(wps[s]);
                ulonglong2 u1 = __ldg(wps[s] + 1);
                ulonglong2 u2 = __ldg(wps[s] + 2);
                // c0 weights: u0.x u0.y u1.x ; c1 weights: u1.y u2.x u2.y
                ffma2(acc[s][0][0], u0.x, a0); ffma2(acc[s][1][0], u0.y, a0); ffma2(acc[s][2][0], u1.x, a0);
                ffma2(acc[s][0][1], u0.x, a1); ffma2(acc[s][1][1], u0.y, a1); ffma2(acc[s][2][1], u1.x, a1);
                ffma2(acc[s][0][2], u0.x, a2); ffma2(acc[s][1][2], u0.y, a2); ffma2(acc[s][2][2], u1.x, a2);
                ffma2(acc[s][0][3], u0.x, a3); ffma2(acc[s][1][3], u0.y, a3); ffma2(acc[s][2][3], u1.x, a3);
                ffma2(acc[s][0][0], u1.y, b0); ffma2(acc[s][1][0], u2.x, b0); ffma2(acc[s][2][0], u2.y, b0);
                ffma2(acc[s][0][1], u1.y, b1); ffma2(acc[s][1][1], u2.x, b1); ffma2(acc[s][2][1], u2.y, b1);
                ffma2(acc[s][0][2], u1.y, b2); ffma2(acc[s][1][2], u2.x, b2); ffma2(acc[s][2][2], u2.y, b2);
                ffma2(acc[s][0][3], u1.y, b3); ffma2(acc[s][1][3], u2.x, b3); ffma2(acc[s][2][3], u2.y, b3);
            }
        }
        float* dsts[3] = {Qs, Ks, Vs};
#pragma unroll
        for (int s = 0; s < 3; s++) {
            float4* d4 = (float4*)dsts[s];
#pragma unroll
            for (int p = 0; p < 3; p++) {
                float2 f0 = ull2f2(acc[s][p][0]), f1 = ull2f2(acc[s][p][1]);
                float2 f2 = ull2f2(acc[s][p][2]), f3 = ull2f2(acc[s][p][3]);
                d4[(rg * 6 + 2 * p) * 16 + cg]     = make_float4(f0.x, f1.x, f2.x, f3.x);
                d4[(rg * 6 + 2 * p + 1) * 16 + cg] = make_float4(f0.y, f1.y, f2.y, f3.y);
            }
        }
    }
    __syncthreads();

    // ---- dwconv 3x3 in place, warp-per-channel, fused sumsq for q,k ----
    {
        int i0 = lane >> 3, j0 = lane & 7;
        int i1 = (lane + 32) >> 3;
#pragma unroll 2
        for (int it = 0; it < 36; it++) {
            int ch = it * 16 + wid;
            float* buf = (ch < 192) ? Qs : (ch < 384) ? Ks : Vs;
            int c = (ch < 192) ? ch : (ch < 384) ? ch - 192 : ch - 384;
            float* rr = buf + c * 64;
            const float* wd = dw_w + (size_t)ch * 9;
            float w[9];
#pragma unroll
            for (int u = 0; u < 9; u++) w[u] = __ldg(wd + u);
            float o0 = 0.f, o1 = 0.f;
#pragma unroll
            for (int di = 0; di < 3; di++) {
#pragma unroll
                for (int dj = 0; dj < 3; dj++) {
                    int jj = j0 + dj - 1;
                    if ((unsigned)jj < 8u) {
                        int ia = i0 + di - 1;
                        if ((unsigned)ia < 8u) o0 += rr[ia * 8 + jj] * w[di * 3 + dj];
                        int ib = i1 + di - 1;
                        if ((unsigned)ib < 8u) o1 += rr[ib * 8 + jj] * w[di * 3 + dj];
                    }
                }
            }
            __syncwarp();
            rr[lane] = o0;
            rr[lane + 32] = o1;
            if (ch < 384) {
                float ss = o0 * o0 + o1 * o1;
                ss += __shfl_xor_sync(0xffffffffu, ss, 16);
                ss += __shfl_xor_sync(0xffffffffu, ss, 8);
                ss += __shfl_xor_sync(0xffffffffu, ss, 4);
                ss += __shfl_xor_sync(0xffffffffu, ss, 2);
                ss += __shfl_xor_sync(0xffffffffu, ss, 1);
                if (lane == 0) Ns[ch] = 1.f / fmaxf(sqrtf(ss), 1e-12f);
            }
            __syncwarp();
        }
    }
    __syncthreads();

    // ---- attn scores on RAW q,k; scale by invq*invk*temp at store ----
    {
        float aacc[6][2];
#pragma unroll
        for (int r = 0; r < 6; r++) { aacc[r][0] = 0.f; aacc[r][1] = 0.f; }
        const float4* q4 = (const float4*)Qs;
        const float4* k4 = (const float4*)Ks;
#pragma unroll 2
        for (int p4 = 0; p4 < 16; p4++) {
#pragma unroll
            for (int r = 0; r < 6; r++) {
                int row = rg * 6 + r;
                int base = row & ~31;
                float4 qv = q4[row * 16 + p4];
#pragma unroll
                for (int cI = 0; cI < 2; cI++) {
                    float4 kv = k4[(base + cg * 2 + cI) * 16 + p4];
                    aacc[r][cI] += qv.x * kv.x + qv.y * kv.y + qv.z * kv.z + qv.w * kv.w;
                }
            }
        }
#pragma unroll
        for (int r = 0; r < 6; r++) {
            int row = rg * 6 + r;
            int base = row & ~31;
            float tmp = __ldg(temperature + (row >> 5));
            float invq = Ns[row];
#pragma unroll
            for (int cI = 0; cI < 2; cI++) {
                int kc = base + cg * 2 + cI;
                As[row * 32 + cg * 2 + cI] = aacc[r][cI] * invq * Ns[192 + kc] * tmp;
            }
        }
    }
    __syncthreads();

    // ---- softmax over d (32), one row per thread ----
    if (tid < DIM) {
        float* arow = As + tid * 32;
        float m = arow[0];
#pragma unroll
        for (int d = 1; d < 32; d++) m = fmaxf(m, arow[d]);
        float s = 0.f;
#pragma unroll
        for (int d = 0; d < 32; d++) { float e = expf(arow[d] - m); arow[d] = e; s += e; }
        float inv = 1.f / s;
#pragma unroll
        for (int d = 0; d < 32; d++) arow[d] *= inv;
    }
    __syncthreads();

    // ---- out = attn @ v -> Xs ----
    {
        ull acc2[6][2];
#pragma unroll
        for (int r = 0; r < 6; r++) { acc2[r][0] = 0ull; acc2[r][1] = 0ull; }
        const ull* v8 = (const ull*)Vs;
        for (int d = 0; d < 32; d++) {
#pragma unroll
            for (int r = 0; r < 6; r++) {
                int row = rg * 6 + r;
                int base = row & ~31;
                ull ad = dup2(As[row * 32 + d]);
                int vb = ((base + d) * 16 + cg) * 2;
                ffma2(acc2[r][0], v8[vb], ad);
                ffma2(acc2[r][1], v8[vb + 1], ad);
            }
        }
        float4* o4 = (float4*)Xs;
#pragma unroll
        for (int r = 0; r < 6; r++) {
            float2 a = ull2f2(acc2[r][0]), b = ull2f2(acc2[r][1]);
            o4[(rg * 6 + r) * 16 + cg] = make_float4(a.x, a.y, b.x, b.y);
        }
    }
    __syncthreads();

    // ---- proj GEMM (paired weights), store to gmem with roll(+4, +4) ----
    {
        ull acc[3][4];
#pragma unroll
        for (int p = 0; p < 3; p++)
#pragma unroll
            for (int j = 0; j < 4; j++) acc[p][j] = 0ull;
        const float4* s4 = (const float4*)Xs;
        const ulonglong2* wpp = (const ulonglong2*)(g_projP + (size_t)rg * 1152);
#pragma unroll 4
        for (int cc = 0; cc < 96; cc++) {
            float4 xa = s4[(2 * cc) * 16 + cg];
            float4 xb = s4[(2 * cc + 1) * 16 + cg];
            ull a0 = dup2(xa.x), a1 = dup2(xa.y), a2 = dup2(xa.z), a3 = dup2(xa.w);
            ull b0 = dup2(xb.x), b1 = dup2(xb.y), b2 = dup2(xb.z), b3 = dup2(xb.w);
            ulonglong2 u0 = __ldg(wpp + cc * 3);
            ulonglong2 u1 = __ldg(wpp + cc * 3 + 1);
            ulonglong2 u2 = __ldg(wpp + cc * 3 + 2);
            ffma2(acc[0][0], u0.x, a0); ffma2(acc[1][0], u0.y, a0); ffma2(acc[2][0], u1.x, a0);
            ffma2(acc[0][1], u0.x, a1); ffma2(acc[1][1], u0.y, a1); ffma2(acc[2][1], u1.x, a1);
            ffma2(acc[0][2], u0.x, a2); ffma2(acc[1][2], u0.y, a2); ffma2(acc[2][2], u1.x, a2);
            ffma2(acc[0][3], u0.x, a3); ffma2(acc[1][3], u0.y, a3); ffma2(acc[2][3], u1.x, a3);
            ffma2(acc[0][0], u1.y, b0); ffma2(acc[1][0], u2.x, b0); ffma2(acc[2][0], u2.y, b0);
            ffma2(acc[0][1], u1.y, b1); ffma2(acc[1][1], u2.x, b1); ffma2(acc[2][1], u2.y, b1);
            ffma2(acc[0][2], u1.y, b2); ffma2(acc[1][2], u2.x, b2); ffma2(acc[2][2], u2.y, b2);
            ffma2(acc[0][3], u1.y, b3); ffma2(acc[1][3], u2.x, b3); ffma2(acc[2][3], u2.y, b3);
        }
        int gh = (wh * WSZ + (cg >> 1) + SHIFTV) & 255;
#pragma unroll
        for (int p = 0; p < 3; p++) {
            float2 f0 = ull2f2(acc[p][0]), f1 = ull2f2(acc[p][1]);
            float2 f2 = ull2f2(acc[p][2]), f3 = ull2f2(acc[p][3]);
            float v0[4] = {f0.x, f1.x, f2.x, f3.x};
            float v1[4] = {f0.y, f1.y, f2.y, f3.y};
            int o0 = rg * 6 + 2 * p;
            float* orow0 = out + ((size_t)(bi * DIM + o0) * IMG + gh) * IMG;
            float* orow1 = out + ((size_t)(bi * DIM + o0 + 1) * IMG + gh) * IMG;
#pragma unroll
            for (int u = 0; u < 4; u++) {
                int j = ((cg & 1) * 4 + u);
                int gw = (ww * WSZ + j + SHIFTV) & 255;
                orow0[gw] = v0[u];
                orow1[gw] = v1[u];
            }
        }
    }
}

extern "C" void kernel_launch(void* const* d_in, const int* in_sizes, int n_in,
                              void* d_out, int out_size) {
    const float* x           = (const float*)d_in[0];
    const float* qkv_w       = (const float*)d_in[1];
    const float* dw_w        = (const float*)d_in[2];
    const float* proj_w      = (const float*)d_in[3];
    const float* temperature = (const float*)d_in[4];
    float* out = (float*)d_out;

    cudaFuncSetAttribute(attn_kernel, cudaFuncAttributeMaxDynamicSharedMemorySize,
                         SMEM_FLOATS * 4);
    wtrans_kernel<<<(96 * 1152 + 255) / 256, 256>>>(qkv_w, proj_w);
    attn_kernel<<<4096, NTHR, SMEM_FLOATS * 4>>>(x, dw_w, temperature, out);
}

// round 5
// speedup vs baseline: 1.0668x; 1.0668x over previous
#include <cuda_runtime.h>

#define DIM   192
#define TDIM  576
#define WSZ   8
#define PIX   64
#define IMG   256
#define SHIFTV 4
#define NTHR  512

// smem layout (floats)
#define XS_OFF 0          // window input, later attention output [192][64]
#define QS_OFF 12288
#define KS_OFF 24576
#define VS_OFF 36864      // v buffer; doubles as weight-staging scratch during GEMMs
#define AS_OFF 49152      // dw-weight staging, then attn scores [192][32]
#define NS_OFF 55296
#define SMEM_FLOATS 55680 // 222720 bytes

typedef unsigned long long ull;

__device__ float g_qkvT[DIM * TDIM];   // [c][o], c-major: chunk of 16 c = 36KB contiguous
__device__ float g_projT[DIM * DIM];   // [c][o]

__global__ void wtrans_kernel(const float* __restrict__ qkv_w,
                              const float* __restrict__ proj_w) {
    int i = blockIdx.x * 256 + threadIdx.x;
    if (i < TDIM * DIM) {
        int o = i / DIM, c = i % DIM;
        g_qkvT[c * TDIM + o] = qkv_w[i];
    }
    if (i < DIM * DIM) {
        int o = i / DIM, c = i % DIM;
        g_projT[c * DIM + o] = proj_w[i];
    }
}

__device__ __forceinline__ ull dup2(float v) {
    ull r;
    asm("mov.b64 %0, {%1, %1};" : "=l"(r) : "f"(v));
    return r;
}
__device__ __forceinline__ void ffma2(ull& d, ull a, ull b) {
    asm("fma.rn.f32x2 %0, %1, %2, %0;" : "+l"(d) : "l"(a), "l"(b));
}
__device__ __forceinline__ float2 ull2f2(ull v) {
    float2 r;
    asm("mov.b64 {%0, %1}, %2;" : "=f"(r.x), "=f"(r.y) : "l"(v));
    return r;
}

__global__ void __launch_bounds__(NTHR, 1)
attn_kernel(const float* __restrict__ x, const float* __restrict__ dw_w,
            const float* __restrict__ temperature, float* __restrict__ out) {
    extern __shared__ float sm[];
    float* Xs = sm + XS_OFF;
    float* Qs = sm + QS_OFF;
    float* Ks = sm + KS_OFF;
    float* Vs = sm + VS_OFF;
    float* As = sm + AS_OFF;
    float* Ns = sm + NS_OFF;
    float* Ws = Vs;            // weight staging alias (Vs free during GEMM mainloops)

    const int tid = threadIdx.x;
    const int win = blockIdx.x;
    const int bi = win >> 10;
    const int wh = (win >> 5) & 31;
    const int ww = win & 31;
    const int rg = tid >> 4;   // 32 groups of 6 rows
    const int cg = tid & 15;   // 16 float4 columns
    const int lane = tid & 31;

    // ---- load window with roll(-4, -4) ----
    {
        const float* xb = x + (size_t)bi * DIM * IMG * IMG;
        for (int e = tid; e < DIM * PIX; e += NTHR) {
            int c = e >> 6, p = e & 63;
            int i = p >> 3, j = p & 7;
            int gh = (wh * WSZ + i + SHIFTV) & 255;
            int gw = (ww * WSZ + j + SHIFTV) & 255;
            Xs[e] = xb[(c * IMG + gh) * IMG + gw];
        }
    }

    // ---- fused qkv GEMM, weights staged through smem in 16-c chunks ----
    {
        ull acc[3][3][4];
#pragma unroll
        for (int s = 0; s < 3; s++)
#pragma unroll
            for (int p = 0; p < 3; p++)
#pragma unroll
                for (int j = 0; j < 4; j++) acc[s][p][j] = 0ull;
        const float4* s4 = (const float4*)Xs;
        for (int kt = 0; kt < 12; kt++) {
            __syncthreads();   // chunk buffer free (also covers window-load on kt=0)
            {
                const float4* src = (const float4*)(g_qkvT + kt * 16 * TDIM);
                float4* dst = (float4*)Ws;
                for (int e = tid; e < 2304; e += NTHR) dst[e] = __ldg(src + e);
            }
            __syncthreads();
#pragma unroll 2
            for (int cl = 0; cl < 16; cl++) {
                int c = kt * 16 + cl;
                float4 xv = s4[c * 16 + cg];
                ull xd0 = dup2(xv.x), xd1 = dup2(xv.y), xd2 = dup2(xv.z), xd3 = dup2(xv.w);
                const float* wb = Ws + cl * TDIM + rg * 6;
#pragma unroll
                for (int s = 0; s < 3; s++) {
                    const ull* wrow = (const ull*)(wb + s * DIM);
                    ull w0 = wrow[0], w1 = wrow[1], w2 = wrow[2];
                    ffma2(acc[s][0][0], w0, xd0); ffma2(acc[s][1][0], w1, xd0); ffma2(acc[s][2][0], w2, xd0);
                    ffma2(acc[s][0][1], w0, xd1); ffma2(acc[s][1][1], w1, xd1); ffma2(acc[s][2][1], w2, xd1);
                    ffma2(acc[s][0][2], w0, xd2); ffma2(acc[s][1][2], w1, xd2); ffma2(acc[s][2][2], w2, xd2);
                    ffma2(acc[s][0][3], w0, xd3); ffma2(acc[s][1][3], w1, xd3); ffma2(acc[s][2][3], w2, xd3);
                }
            }
        }
        __syncthreads();   // all reads of Ws done before Vs is written
        float* dsts[3] = {Qs, Ks, Vs};
#pragma unroll
        for (int s = 0; s < 3; s++) {
            float4* d4 = (float4*)dsts[s];
#pragma unroll
            for (int p = 0; p < 3; p++) {
                float2 f0 = ull2f2(acc[s][p][0]), f1 = ull2f2(acc[s][p][1]);
                float2 f2 = ull2f2(acc[s][p][2]), f3 = ull2f2(acc[s][p][3]);
                d4[(rg * 6 + 2 * p) * 16 + cg]     = make_float4(f0.x, f1.x, f2.x, f3.x);
                d4[(rg * 6 + 2 * p + 1) * 16 + cg] = make_float4(f0.y, f1.y, f2.y, f3.y);
            }
        }
    }

    // ---- stage dw weights (576*9 floats) into As ----
    {
        const float4* src = (const float4*)dw_w;
        float4* dst = (float4*)As;
        for (int e = tid; e < 1296; e += NTHR) dst[e] = __ldg(src + e);
    }
    __syncthreads();

    // ---- dwconv 3x3 in place, one thread per (channel,row), fused sumsq ----
    {
#pragma unroll
        for (int it = 0; it < 9; it++) {
            int t = it * NTHR + tid;
            int ch = t >> 3, row = t & 7;
            float* buf = (ch < 192) ? Qs : (ch < 384) ? Ks : Vs;
            int c = (ch < 192) ? ch : (ch < 384) ? ch - 192 : ch - 384;
            float* rr = buf + c * 64;
            const float* wd = As + ch * 9;
            float w0 = wd[0], w1 = wd[1], w2 = wd[2];
            float w3 = wd[3], w4 = wd[4], w5 = wd[5];
            float w6 = wd[6], w7 = wd[7], w8 = wd[8];
            float A[8], B[8], C[8];
            {
                const float4* r4 = (const float4*)(rr + row * 8);
                float4 b0 = r4[0], b1 = r4[1];
                B[0]=b0.x; B[1]=b0.y; B[2]=b0.z; B[3]=b0.w;
                B[4]=b1.x; B[5]=b1.y; B[6]=b1.z; B[7]=b1.w;
            }
            if (row > 0) {
                const float4* r4 = (const float4*)(rr + (row - 1) * 8);
                float4 a0 = r4[0], a1 = r4[1];
                A[0]=a0.x; A[1]=a0.y; A[2]=a0.z; A[3]=a0.w;
                A[4]=a1.x; A[5]=a1.y; A[6]=a1.z; A[7]=a1.w;
            } else {
#pragma unroll
                for (int j = 0; j < 8; j++) A[j] = 0.f;
            }
            if (row < 7) {
                const float4* r4 = (const float4*)(rr + (row + 1) * 8);
                float4 c0 = r4[0], c1 = r4[1];
                C[0]=c0.x; C[1]=c0.y; C[2]=c0.z; C[3]=c0.w;
                C[4]=c1.x; C[5]=c1.y; C[6]=c1.z; C[7]=c1.w;
            } else {
#pragma unroll
                for (int j = 0; j < 8; j++) C[j] = 0.f;
            }
            float o[8];
            float ss = 0.f;
#pragma unroll
            for (int j = 0; j < 8; j++) {
                float s = w1 * A[j] + w4 * B[j] + w7 * C[j];
                if (j > 0) s += w0 * A[j-1] + w3 * B[j-1] + w6 * C[j-1];
                if (j < 7) s += w2 * A[j+1] + w5 * B[j+1] + w8 * C[j+1];
                o[j] = s;
                ss += s * s;
            }
            ss += __shfl_xor_sync(0xffffffffu, ss, 4);
            ss += __shfl_xor_sync(0xffffffffu, ss, 2);
            ss += __shfl_xor_sync(0xffffffffu, ss, 1);
            __syncwarp();
            float4* w4p = (float4*)(rr + row * 8);
            w4p[0] = make_float4(o[0], o[1], o[2], o[3]);
            w4p[1] = make_float4(o[4], o[5], o[6], o[7]);
            if ((lane & 7) == 0 && ch < 384)
                Ns[ch] = 1.f / fmaxf(sqrtf(ss), 1e-12f);
            __syncwarp();
        }
    }
    __syncthreads();

    // ---- attn scores on RAW q,k; scale by invq*invk*temp at store ----
    {
        float aacc[6][2];
#pragma unroll
        for (int r = 0; r < 6; r++) { aacc[r][0] = 0.f; aacc[r][1] = 0.f; }
        const float4* q4 = (const float4*)Qs;
        const float4* k4 = (const float4*)Ks;
#pragma unroll 2
        for (int p4 = 0; p4 < 16; p4++) {
#pragma unroll
            for (int r = 0; r < 6; r++) {
                int row = rg * 6 + r;
                int base = row & ~31;
                float4 qv = q4[row * 16 + p4];
#pragma unroll
                for (int cI = 0; cI < 2; cI++) {
                    float4 kv = k4[(base + cg * 2 + cI) * 16 + p4];
                    aacc[r][cI] += qv.x * kv.x + qv.y * kv.y + qv.z * kv.z + qv.w * kv.w;
                }
            }
        }
        __syncthreads();   // As (dw weights) no longer needed; reuse for scores
#pragma unroll
        for (int r = 0; r < 6; r++) {
            int row = rg * 6 + r;
            int base = row & ~31;
            float tmp = __ldg(temperature + (row >> 5));
            float invq = Ns[row];
#pragma unroll
            for (int cI = 0; cI < 2; cI++) {
                int kc = base + cg * 2 + cI;
                As[row * 32 + cg * 2 + cI] = aacc[r][cI] * invq * Ns[192 + kc] * tmp;
            }
        }
    }
    __syncthreads();

    // ---- softmax over d (32), one row per thread ----
    if (tid < DIM) {
        float* arow = As + tid * 32;
        float m = arow[0];
#pragma unroll
        for (int d = 1; d < 32; d++) m = fmaxf(m, arow[d]);
        float s = 0.f;
#pragma unroll
        for (int d = 0; d < 32; d++) { float e = expf(arow[d] - m); arow[d] = e; s += e; }
        float inv = 1.f / s;
#pragma unroll
        for (int d = 0; d < 32; d++) arow[d] *= inv;
    }
    __syncthreads();

    // ---- out = attn @ v -> Xs ----
    {
        ull acc2[6][2];
#pragma unroll
        for (int r = 0; r < 6; r++) { acc2[r][0] = 0ull; acc2[r][1] = 0ull; }
        const ull* v8 = (const ull*)Vs;
        for (int d = 0; d < 32; d++) {
#pragma unroll
            for (int r = 0; r < 6; r++) {
                int row = rg * 6 + r;
                int base = row & ~31;
                ull ad = dup2(As[row * 32 + d]);
                int vb = ((base + d) * 16 + cg) * 2;
                ffma2(acc2[r][0], v8[vb], ad);
                ffma2(acc2[r][1], v8[vb + 1], ad);
            }
        }
        __syncthreads();   // everyone done reading Vs/As before Xs rewrite is fine; Xs overwrite below
        float4* o4 = (float4*)Xs;
#pragma unroll
        for (int r = 0; r < 6; r++) {
            float2 a = ull2f2(acc2[r][0]), b = ull2f2(acc2[r][1]);
            o4[(rg * 6 + r) * 16 + cg] = make_float4(a.x, a.y, b.x, b.y);
        }
    }

    // ---- proj GEMM, weights staged through smem (32-c chunks in Vs) ----
    {
        ull acc[3][4];
#pragma unroll
        for (int p = 0; p < 3; p++)
#pragma unroll
            for (int j = 0; j < 4; j++) acc[p][j] = 0ull;
        const float4* s4 = (const float4*)Xs;
        for (int kt = 0; kt < 6; kt++) {
            __syncthreads();   // previous chunk consumed / Vs free (first iter: after attn@v)
            {
                const float4* src = (const float4*)(g_projT + kt * 32 * DIM);
                float4* dst = (float4*)Ws;
                for (int e = tid; e < 1536; e += NTHR) dst[e] = __ldg(src + e);
            }
            __syncthreads();
#pragma unroll 4
            for (int cl = 0; cl < 32; cl++) {
                int c = kt * 32 + cl;
                float4 xv = s4[c * 16 + cg];
                ull xd0 = dup2(xv.x), xd1 = dup2(xv.y), xd2 = dup2(xv.z), xd3 = dup2(xv.w);
                const ull* wrow = (const ull*)(Ws + cl * DIM + rg * 6);
                ull w0 = wrow[0], w1 = wrow[1], w2 = wrow[2];
                ffma2(acc[0][0], w0, xd0); ffma2(acc[1][0], w1, xd0); ffma2(acc[2][0], w2, xd0);
                ffma2(acc[0][1], w0, xd1); ffma2(acc[1][1], w1, xd1); ffma2(acc[2][1], w2, xd1);
                ffma2(acc[0][2], w0, xd2); ffma2(acc[1][2], w1, xd2); ffma2(acc[2][2], w2, xd2);
                ffma2(acc[0][3], w0, xd3); ffma2(acc[1][3], w1, xd3); ffma2(acc[2][3], w2, xd3);
            }
        }
        int gh = (wh * WSZ + (cg >> 1) + SHIFTV) & 255;
#pragma unroll
        for (int p = 0; p < 3; p++) {
            float2 f0 = ull2f2(acc[p][0]), f1 = ull2f2(acc[p][1]);
            float2 f2 = ull2f2(acc[p][2]), f3 = ull2f2(acc[p][3]);
            float v0[4] = {f0.x, f1.x, f2.x, f3.x};
            float v1[4] = {f0.y, f1.y, f2.y, f3.y};
            int o0 = rg * 6 + 2 * p;
            float* orow0 = out + ((size_t)(bi * DIM + o0) * IMG + gh) * IMG;
            float* orow1 = out + ((size_t)(bi * DIM + o0 + 1) * IMG + gh) * IMG;
#pragma unroll
            for (int u = 0; u < 4; u++) {
                int j = ((cg & 1) * 4 + u);
                int gw = (ww * WSZ + j + SHIFTV) & 255;
                orow0[gw] = v0[u];
                orow1[gw] = v1[u];
            }
        }
    }
}

extern "C" void kernel_launch(void* const* d_in, const int* in_sizes, int n_in,
                              void* d_out, int out_size) {
    const float* x           = (const float*)d_in[0];
    const float* qkv_w       = (const float*)d_in[1];
    const float* dw_w        = (const float*)d_in[2];
    const float* proj_w      = (const float*)d_in[3];
    const float* temperature = (const float*)d_in[4];
    float* out = (float*)d_out;

    cudaFuncSetAttribute(attn_kernel, cudaFuncAttributeMaxDynamicSharedMemorySize,
                         SMEM_FLOATS * 4);
    wtrans_kernel<<<(TDIM * DIM + 255) / 256, 256>>>(qkv_w, proj_w);
    attn_kernel<<<4096, NTHR, SMEM_FLOATS * 4>>>(x, dw_w, temperature, out);
}

// round 7
// speedup vs baseline: 1.6031x; 1.5027x over previous
#include <cuda_runtime.h>

#define DIM   192
#define TDIM  576
#define WSZ   8
#define PIX   64
#define IMG   256
#define SHIFTV 4
#define NTHR  512

#define STRC  68
#define STRC4 17
#define STRK  196
#define STRA  33

#define A_OFF  0
#define B_OFF  12544
#define C_OFF  25600
#define D_OFF  38656
#define NS_OFF 51712
#define SMEM_FLOATS 52160

typedef unsigned long long ull;

__device__ float g_qkvT[DIM * TDIM];
__device__ float g_projT[DIM * DIM];

__global__ void wtrans_kernel(const float* __restrict__ qkv_w,
                              const float* __restrict__ proj_w) {
    int i = blockIdx.x * 256 + threadIdx.x;
    if (i < TDIM * DIM) {
        int o = i / DIM, c = i % DIM;
        g_qkvT[c * TDIM + o] = qkv_w[i];
    }
    if (i < DIM * DIM) {
        int o = i / DIM, c = i % DIM;
        g_projT[c * DIM + o] = proj_w[i];
    }
}

__device__ __forceinline__ ull dup2(float v) {
    ull r;
    asm("mov.b64 %0, {%1, %1};" : "=l"(r) : "f"(v));
    return r;
}
__device__ __forceinline__ void ffma2(ull& d, ull a, ull b) {
    asm("fma.rn.f32x2 %0, %1, %2, %0;" : "+l"(d) : "l"(a), "l"(b));
}
__device__ __forceinline__ float2 ull2f2(ull v) {
    float2 r;
    asm("mov.b64 {%0, %1}, %2;" : "=f"(r.x), "=f"(r.y) : "l"(v));
    return r;
}

__global__ void __launch_bounds__(NTHR, 1)
attn_kernel(const float* __restrict__ x, const float* __restrict__ dw_w,
            const float* __restrict__ temperature, float* __restrict__ out) {
    extern __shared__ float sm[];
    float* Ra = sm + A_OFF;
    float* Rb = sm + B_OFF;
    float* Rc = sm + C_OFF;
    float* Rd = sm + D_OFF;
    float* Ns = sm + NS_OFF;

    const int tid = threadIdx.x;
    const int win = blockIdx.x;
    const int bi = win >> 10;
    const int wh = (win >> 5) & 31;
    const int ww = win & 31;
    const int rg = tid >> 4;
    const int cg = tid & 15;
    const int lane = tid & 31;

    if (tid < DIM) Ns[DIM + tid] = 0.f;

    // ---- load window with roll(-4,-4) into Ra (Xs [192][64]) ----
    {
        const float* xb = x + (size_t)bi * DIM * IMG * IMG;
        for (int e = tid; e < DIM * PIX; e += NTHR) {
            int c = e >> 6, p = e & 63;
            int i = p >> 3, j = p & 7;
            int gh = (wh * WSZ + i + SHIFTV) & 255;
            int gw = (ww * WSZ + j + SHIFTV) & 255;
            Ra[e] = xb[(c * IMG + gh) * IMG + gw];
        }
    }

    // ---- fused qkv GEMM, double-buffered 16-c weight chunks ----
    {
        float* W0 = Rb;
        float* W1 = Rb + 9216;
        ull acc[3][3][4];
#pragma unroll
        for (int s = 0; s < 3; s++)
#pragma unroll
            for (int p = 0; p < 3; p++)
#pragma unroll
                for (int j = 0; j < 4; j++) acc[s][p][j] = 0ull;
        const float4* s4 = (const float4*)Ra;
        const float4* gw = (const float4*)g_qkvT;
        {
            float4* dst = (float4*)W0;
            for (int e = tid; e < 2304; e += NTHR) dst[e] = __ldg(gw + e);
        }
        __syncthreads();
        for (int kt = 0; kt < 12; kt++) {
            const float* Wcur = (kt & 1) ? W1 : W0;
            if (kt < 11) {
                float4* dst = (float4*)((kt & 1) ? W0 : W1);
                const float4* src = gw + (kt + 1) * 2304;
                for (int e = tid; e < 2304; e += NTHR) dst[e] = __ldg(src + e);
            }
#pragma unroll 2
            for (int cl = 0; cl < 16; cl++) {
                int c = kt * 16 + cl;
                float4 xv = s4[c * 16 + cg];
                ull xd0 = dup2(xv.x), xd1 = dup2(xv.y), xd2 = dup2(xv.z), xd3 = dup2(xv.w);
                const float* wb = Wcur + cl * TDIM + rg * 6;
#pragma unroll
                for (int s = 0; s < 3; s++) {
                    const ull* wrow = (const ull*)(wb + s * DIM);
                    ull w0 = wrow[0], w1 = wrow[1], w2 = wrow[2];
                    ffma2(acc[s][0][0], w0, xd0); ffma2(acc[s][1][0], w1, xd0); ffma2(acc[s][2][0], w2, xd0);
                    ffma2(acc[s][0][1], w0, xd1); ffma2(acc[s][1][1], w1, xd1); ffma2(acc[s][2][1], w2, xd1);
                    ffma2(acc[s][0][2], w0, xd2); ffma2(acc[s][1][2], w1, xd2); ffma2(acc[s][2][2], w2, xd2);
                    ffma2(acc[s][0][3], w0, xd3); ffma2(acc[s][1][3], w1, xd3); ffma2(acc[s][2][3], w2, xd3);
                }
            }
            __syncthreads();
        }
        float* dsts[3] = {Rb, Rc, Rd};
#pragma unroll
        for (int s = 0; s < 3; s++) {
            float4* d4 = (float4*)dsts[s];
#pragma unroll
            for (int p = 0; p < 3; p++) {
                float2 f0 = ull2f2(acc[s][p][0]), f1 = ull2f2(acc[s][p][1]);
                float2 f2 = ull2f2(acc[s][p][2]), f3 = ull2f2(acc[s][p][3]);
                d4[(rg * 6 + 2 * p) * STRC4 + cg]     = make_float4(f0.x, f1.x, f2.x, f3.x);
                d4[(rg * 6 + 2 * p + 1) * STRC4 + cg] = make_float4(f0.y, f1.y, f2.y, f3.y);
            }
        }
    }
    __syncthreads();

    // ---- dwconv Q,V in place; K -> transposed Kt in Ra ----
    {
#pragma unroll
        for (int it = 0; it < 6; it++) {
            int t = it * NTHR + tid;
            int ch_ = t >> 3, row = t & 7;
            int isQ = ch_ < DIM;
            float* rr = (isQ ? Rb : Rd) + (isQ ? ch_ : ch_ - DIM) * STRC;
            // Q channels: dw 0..191.  V tensor channel (ch_-192) -> dw 384+(ch_-192) = ch_+DIM
            int dwc = isQ ? ch_ : ch_ + DIM;
            const float* wd = dw_w + (size_t)dwc * 9;
            float w0 = __ldg(wd+0), w1 = __ldg(wd+1), w2 = __ldg(wd+2);
            float w3 = __ldg(wd+3), w4 = __ldg(wd+4), w5 = __ldg(wd+5);
            float w6 = __ldg(wd+6), w7 = __ldg(wd+7), w8 = __ldg(wd+8);
            float A[8], B[8], C[8];
            {
                const float4* r4 = (const float4*)(rr + row * 8);
                float4 b0 = r4[0], b1 = r4[1];
                B[0]=b0.x; B[1]=b0.y; B[2]=b0.z; B[3]=b0.w;
                B[4]=b1.x; B[5]=b1.y; B[6]=b1.z; B[7]=b1.w;
            }
            if (row > 0) {
                const float4* r4 = (const float4*)(rr + (row - 1) * 8);
                float4 a0 = r4[0], a1 = r4[1];
                A[0]=a0.x; A[1]=a0.y; A[2]=a0.z; A[3]=a0.w;
                A[4]=a1.x; A[5]=a1.y; A[6]=a1.z; A[7]=a1.w;
            } else {
#pragma unroll
                for (int j = 0; j < 8; j++) A[j] = 0.f;
            }
            if (row < 7) {
                const float4* r4 = (const float4*)(rr + (row + 1) * 8);
                float4 c0 = r4[0], c1 = r4[1];
                C[0]=c0.x; C[1]=c0.y; C[2]=c0.z; C[3]=c0.w;
                C[4]=c1.x; C[5]=c1.y; C[6]=c1.z; C[7]=c1.w;
            } else {
#pragma unroll
                for (int j = 0; j < 8; j++) C[j] = 0.f;
            }
            float o[8];
            float ss = 0.f;
#pragma unroll
            for (int j = 0; j < 8; j++) {
                float s = w1 * A[j] + w4 * B[j] + w7 * C[j];
                if (j > 0) s += w0 * A[j-1] + w3 * B[j-1] + w6 * C[j-1];
                if (j < 7) s += w2 * A[j+1] + w5 * B[j+1] + w8 * C[j+1];
                o[j] = s;
                ss += s * s;
            }
            ss += __shfl_xor_sync(0xffffffffu, ss, 4);
            ss += __shfl_xor_sync(0xffffffffu, ss, 2);
            ss += __shfl_xor_sync(0xffffffffu, ss, 1);
            __syncwarp();
            float4* w4p = (float4*)(rr + row * 8);
            w4p[0] = make_float4(o[0], o[1], o[2], o[3]);
            w4p[1] = make_float4(o[4], o[5], o[6], o[7]);
            if (isQ && (lane & 7) == 0)
                Ns[ch_] = 1.f / fmaxf(sqrtf(ss), 1e-12f);
            __syncwarp();
        }
#pragma unroll
        for (int it = 0; it < 3; it++) {
            int task = it * NTHR + tid;
            int ch = task % DIM;
            int row = task / DIM;
            const float* rr = Rc + ch * STRC;
            const float* wd = dw_w + (size_t)(DIM + ch) * 9;
            float w0 = __ldg(wd+0), w1 = __ldg(wd+1), w2 = __ldg(wd+2);
            float w3 = __ldg(wd+3), w4 = __ldg(wd+4), w5 = __ldg(wd+5);
            float w6 = __ldg(wd+6), w7 = __ldg(wd+7), w8 = __ldg(wd+8);
            float A[8], B[8], C[8];
            {
                const float4* r4 = (const float4*)(rr + row * 8);
                float4 b0 = r4[0], b1 = r4[1];
                B[0]=b0.x; B[1]=b0.y; B[2]=b0.z; B[3]=b0.w;
                B[4]=b1.x; B[5]=b1.y; B[6]=b1.z; B[7]=b1.w;
            }
            if (row > 0) {
                const float4* r4 = (const float4*)(rr + (row - 1) * 8);
                float4 a0 = r4[0], a1 = r4[1];
                A[0]=a0.x; A[1]=a0.y; A[2]=a0.z; A[3]=a0.w;
                A[4]=a1.x; A[5]=a1.y; A[6]=a1.z; A[7]=a1.w;
            } else {
#pragma unroll
                for (int j = 0; j < 8; j++) A[j] = 0.f;
            }
            if (row < 7) {
                const float4* r4 = (const float4*)(rr + (row + 1) * 8);
                float4 c0 = r4[0], c1 = r4[1];
                C[0]=c0.x; C[1]=c0.y; C[2]=c0.z; C[3]=c0.w;
                C[4]=c1.x; C[5]=c1.y; C[6]=c1.z; C[7]=c1.w;
            } else {
#pragma unroll
                for (int j = 0; j < 8; j++) C[j] = 0.f;
            }
            float ss = 0.f;
#pragma unroll
            for (int j = 0; j < 8; j++) {
                float s = w1 * A[j] + w4 * B[j] + w7 * C[j];
                if (j > 0) s += w0 * A[j-1] + w3 * B[j-1] + w6 * C[j-1];
                if (j < 7) s += w2 * A[j+1] + w5 * B[j+1] + w8 * C[j+1];
                Ra[(row * 8 + j) * STRK + ch] = s;
                ss += s * s;
            }
            atomicAdd(&Ns[DIM + ch], ss);
        }
    }
    __syncthreads();

    if (tid < DIM) Ns[DIM + tid] = 1.f / fmaxf(sqrtf(Ns[DIM + tid]), 1e-12f);
    __syncthreads();

    // ---- scores: Q (Rb, ch-major) x Kt (Ra, px-major) -> As (Rc) ----
    {
        float* As = Rc;
        const int rgr = tid >> 3;
        const int kg = tid & 7;
        int rows[3] = {rgr, rgr + 64, rgr + 128};
        ull acc[3][2];
#pragma unroll
        for (int j = 0; j < 3; j++) { acc[j][0] = 0ull; acc[j][1] = 0ull; }
        int kc[3];
#pragma unroll
        for (int j = 0; j < 3; j++) kc[j] = (rows[j] & ~31) + kg * 4;
#pragma unroll 4
        for (int p = 0; p < 64; p++) {
            const float* ktp = Ra + p * STRK;
#pragma unroll
            for (int j = 0; j < 3; j++) {
                ull qd = dup2(Rb[rows[j] * STRC + p]);
                const ull* kv = (const ull*)(ktp + kc[j]);
                ffma2(acc[j][0], kv[0], qd);
                ffma2(acc[j][1], kv[1], qd);
            }
        }
#pragma unroll
        for (int j = 0; j < 3; j++) {
            int row = rows[j];
            float tmp = __ldg(temperature + (row >> 5));
            float invq = Ns[row] * tmp;
            float2 f0 = ull2f2(acc[j][0]), f1 = ull2f2(acc[j][1]);
            float* arow = As + row * STRA + kg * 4;
            arow[0] = f0.x * invq * Ns[DIM + kc[j]];
            arow[1] = f0.y * invq * Ns[DIM + kc[j] + 1];
            arow[2] = f1.x * invq * Ns[DIM + kc[j] + 2];
            arow[3] = f1.y * invq * Ns[DIM + kc[j] + 3];
        }
    }
    __syncthreads();

    // ---- softmax (stride-33 rows: conflict free) ----
    if (tid < DIM) {
        float* arow = Rc + tid * STRA;
        float m = arow[0];
#pragma unroll
        for (int d = 1; d < 32; d++) m = fmaxf(m, arow[d]);
        float s = 0.f;
#pragma unroll
        for (int d = 0; d < 32; d++) { float e = expf(arow[d] - m); arow[d] = e; s += e; }
        float inv = 1.f / s;
#pragma unroll
        for (int d = 0; d < 32; d++) arow[d] *= inv;
    }
    __syncthreads();

    // ---- out = attn @ v -> Ra [192][64] ----
    {
        ull acc2[6][2];
#pragma unroll
        for (int r = 0; r < 6; r++) { acc2[r][0] = 0ull; acc2[r][1] = 0ull; }
        const ull* v8 = (const ull*)Rd;
        const float* As = Rc;
        for (int d = 0; d < 32; d++) {
#pragma unroll
            for (int r = 0; r < 6; r++) {
                int row = rg * 6 + r;
                int base = row & ~31;
                ull ad = dup2(As[row * STRA + d]);
                int vb = (base + d) * (STRC / 2) + cg * 2;
                ffma2(acc2[r][0], v8[vb], ad);
                ffma2(acc2[r][1], v8[vb + 1], ad);
            }
        }
        float4* o4 = (float4*)Ra;
#pragma unroll
        for (int r = 0; r < 6; r++) {
            float2 a = ull2f2(acc2[r][0]), b = ull2f2(acc2[r][1]);
            o4[(rg * 6 + r) * 16 + cg] = make_float4(a.x, a.y, b.x, b.y);
        }
    }
    __syncthreads();

    // ---- proj GEMM, double-buffered staging in Rc ----
    {
        float* P0 = Rc;
        float* P1 = Rc + 6144;
        ull acc[3][4];
#pragma unroll
        for (int p = 0; p < 3; p++)
#pragma unroll
            for (int j = 0; j < 4; j++) acc[p][j] = 0ull;
        const float4* s4 = (const float4*)Ra;
        const float4* gp = (const float4*)g_projT;
        {
            float4* dst = (float4*)P0;
            for (int e = tid; e < 1536; e += NTHR) dst[e] = __ldg(gp + e);
        }
        __syncthreads();
        for (int kt = 0; kt < 6; kt++) {
            const float* Pcur = (kt & 1) ? P1 : P0;
            if (kt < 5) {
                float4* dst = (float4*)((kt & 1) ? P0 : P1);
                const float4* src = gp + (kt + 1) * 1536;
                for (int e = tid; e < 1536; e += NTHR) dst[e] = __ldg(src + e);
            }
#pragma unroll 4
            for (int cl = 0; cl < 32; cl++) {
                int c = kt * 32 + cl;
                float4 xv = s4[c * 16 + cg];
                ull xd0 = dup2(xv.x), xd1 = dup2(xv.y), xd2 = dup2(xv.z), xd3 = dup2(xv.w);
                const ull* wrow = (const ull*)(Pcur + cl * DIM + rg * 6);
                ull w0 = wrow[0], w1 = wrow[1], w2 = wrow[2];
                ffma2(acc[0][0], w0, xd0); ffma2(acc[1][0], w1, xd0); ffma2(acc[2][0], w2, xd0);
                ffma2(acc[0][1], w0, xd1); ffma2(acc[1][1], w1, xd1); ffma2(acc[2][1], w2, xd1);
                ffma2(acc[0][2], w0, xd2); ffma2(acc[1][2], w1, xd2); ffma2(acc[2][2], w2, xd2);
                ffma2(acc[0][3], w0, xd3); ffma2(acc[1][3], w1, xd3); ffma2(acc[2][3], w2, xd3);
            }
            __syncthreads();
        }
        int gh = (wh * WSZ + (cg >> 1) + SHIFTV) & 255;
#pragma unroll
        for (int p = 0; p < 3; p++) {
            float2 f0 = ull2f2(acc[p][0]), f1 = ull2f2(acc[p][1]);
            float2 f2 = ull2f2(acc[p][2]), f3 = ull2f2(acc[p][3]);
            float v0[4] = {f0.x, f1.x, f2.x, f3.x};
            float v1[4] = {f0.y, f1.y, f2.y, f3.y};
            int o0 = rg * 6 + 2 * p;
            float* orow0 = out + ((size_t)(bi * DIM + o0) * IMG + gh) * IMG;
            float* orow1 = out + ((size_t)(bi * DIM + o0 + 1) * IMG + gh) * IMG;
#pragma unroll
            for (int u = 0; u < 4; u++) {
                int j = ((cg & 1) * 4 + u);
                int gw = (ww * WSZ + j + SHIFTV) & 255;
                orow0[gw] = v0[u];
                orow1[gw] = v1[u];
            }
        }
    }
}

extern "C" void kernel_launch(void* const* d_in, const int* in_sizes, int n_in,
                              void* d_out, int out_size) {
    const float* x           = (const float*)d_in[0];
    const float* qkv_w       = (const float*)d_in[1];
    const float* dw_w        = (const float*)d_in[2];
    const float* proj_w      = (const float*)d_in[3];
    const float* temperature = (const float*)d_in[4];
    float* out = (float*)d_out;

    cudaFuncSetAttribute(attn_kernel, cudaFuncAttributeMaxDynamicSharedMemorySize,
                         SMEM_FLOATS * 4);
    wtrans_kernel<<<(TDIM * DIM + 255) / 256, 256>>>(qkv_w, proj_w);
    attn_kernel<<<4096, NTHR, SMEM_FLOATS * 4>>>(x, dw_w, temperature, out);
}

// round 9
// speedup vs baseline: 2.0681x; 1.2901x over previous
#include <cuda_runtime.h>
#include <cstdint>

#define DIM   192
#define TDIM  576
#define WSZ   8
#define PIX   64
#define IMG   256
#define SHIFTV 4
#define NTHR  512

#define STRC  68
#define STRK  196
#define STRA  33
#define WSTR  648     // staged weight chunk col stride (==8 mod 32: conflict-free A lds)

#define A_OFF  0      // Ws0 chunk -> Kt[64][196] -> attn-out[192][64]
#define B_OFF  12544  // Xb tf32 [192][68] -> Q [192][68]
#define C_OFF  25600  // Ws1 chunk -> rawK [192][68] -> As[192][33] -> proj staging
#define D_OFF  38656  // rawV/V [192][68]
#define NS_OFF 51712
#define SMEM_FLOATS 52160

typedef unsigned long long ull;

__device__ uint32_t g_qkvK[DIM * 640];   // k-major tf32: [c][o], o>=576 zero
__device__ float    g_projT[DIM * DIM];  // [c][o]

__device__ __forceinline__ uint32_t f2tf32(float f) {
    uint32_t u; asm("cvt.rna.tf32.f32 %0, %1;" : "=r"(u) : "f"(f)); return u;
}

__global__ void wtrans_kernel(const float* __restrict__ qkv_w,
                              const float* __restrict__ proj_w) {
    int i = blockIdx.x * 256 + threadIdx.x;
    if (i < DIM * 640) {
        int c = i / 640, o = i % 640;
        g_qkvK[i] = (o < TDIM) ? f2tf32(qkv_w[o * DIM + c]) : 0u;
    }
    if (i < DIM * DIM) {
        int o = i / DIM, c = i % DIM;
        g_projT[c * DIM + o] = proj_w[i];
    }
}

__device__ __forceinline__ ull dup2(float v) {
    ull r; asm("mov.b64 %0, {%1, %1};" : "=l"(r) : "f"(v)); return r;
}
__device__ __forceinline__ void ffma2(ull& d, ull a, ull b) {
    asm("fma.rn.f32x2 %0, %1, %2, %0;" : "+l"(d) : "l"(a), "l"(b));
}
__device__ __forceinline__ float2 ull2f2(ull v) {
    float2 r; asm("mov.b64 {%0, %1}, %2;" : "=f"(r.x), "=f"(r.y) : "l"(v)); return r;
}
__device__ __forceinline__ void mma16n8k8(float* d, const uint32_t* a, const uint32_t* b) {
    asm volatile(
        "mma.sync.aligned.m16n8k8.row.col.f32.tf32.tf32.f32 "
        "{%0,%1,%2,%3}, {%4,%5,%6,%7}, {%8,%9}, {%0,%1,%2,%3};"
        : "+f"(d[0]), "+f"(d[1]), "+f"(d[2]), "+f"(d[3])
        : "r"(a[0]), "r"(a[1]), "r"(a[2]), "r"(a[3]), "r"(b[0]), "r"(b[1]));
}

__global__ void __launch_bounds__(NTHR, 1)
attn_kernel(const float* __restrict__ x, const float* __restrict__ dw_w,
            const float* __restrict__ temperature, float* __restrict__ out) {
    extern __shared__ float sm[];
    float* Ra = sm + A_OFF;
    float* Rb = sm + B_OFF;
    float* Rc = sm + C_OFF;
    float* Rd = sm + D_OFF;
    float* Ns = sm + NS_OFF;

    const int tid = threadIdx.x;
    const int win = blockIdx.x;
    const int bi = win >> 10;
    const int wh = (win >> 5) & 31;
    const int ww = win & 31;
    const int rg = tid >> 4;
    const int cg = tid & 15;
    const int lane = tid & 31;
    const int wid = tid >> 5;

    if (tid < DIM) Ns[DIM + tid] = 0.f;

    // ---- load window with roll(-4,-4) into Rb as tf32 bits [192][68] ----
    {
        const float* xb = x + (size_t)bi * DIM * IMG * IMG;
        uint32_t* Xu = (uint32_t*)Rb;
        for (int e = tid; e < DIM * PIX; e += NTHR) {
            int c = e >> 6, p = e & 63;
            int i = p >> 3, j = p & 7;
            int gh = (wh * WSZ + i + SHIFTV) & 255;
            int gw = (ww * WSZ + j + SHIFTV) & 255;
            Xu[c * STRC + p] = f2tf32(xb[(c * IMG + gh) * IMG + gw]);
        }
    }

    // ---- qkv GEMM via mma.sync tf32 (tensor pipe) ----
    {
        const uint32_t* Xu = (const uint32_t*)Rb;
        const int gid = lane >> 2, tig = lane & 3;
        const int mg = wid >> 1, ng = wid & 1;
        float dacc[5][4][4];
#pragma unroll
        for (int mt = 0; mt < 5; mt++)
#pragma unroll
            for (int nt = 0; nt < 4; nt++)
#pragma unroll
                for (int q = 0; q < 4; q++) dacc[mt][nt][q] = 0.f;

        // stage chunk 0 into Ra
        {
            const uint4* src = (const uint4*)g_qkvK;
            for (int e = tid; e < 2560; e += NTHR) {
                int r = e / 160, c4 = e - r * 160;
                ((uint4*)((uint32_t*)Ra + r * WSTR))[c4] = __ldg(src + e);
            }
        }
        __syncthreads();

        for (int kc = 0; kc < 12; kc++) {
            const uint32_t* Wc = (const uint32_t*)((kc & 1) ? Rc : Ra);
            if (kc < 11) {
                uint32_t* Wn = (uint32_t*)((kc & 1) ? Ra : Rc);
                const uint4* src = (const uint4*)(g_qkvK + (size_t)(kc + 1) * 16 * 640);
                for (int e = tid; e < 2560; e += NTHR) {
                    int r = e / 160, c4 = e - r * 160;
                    ((uint4*)(Wn + r * WSTR))[c4] = __ldg(src + e);
                }
            }
#pragma unroll
            for (int ks = 0; ks < 2; ks++) {
                const int kk = ks * 8;
                uint32_t breg[4][2];
#pragma unroll
                for (int nt = 0; nt < 4; nt++) {
                    int col = ng * 32 + nt * 8 + gid;
                    breg[nt][0] = Xu[(kc * 16 + kk + tig) * STRC + col];
                    breg[nt][1] = Xu[(kc * 16 + kk + tig + 4) * STRC + col];
                }
#pragma unroll
                for (int mt = 0; mt < 5; mt++) {
                    int mcol = mg * 80 + mt * 16 + gid;
                    uint32_t areg[4];
                    areg[0] = Wc[(kk + tig) * WSTR + mcol];
                    areg[1] = Wc[(kk + tig) * WSTR + mcol + 8];
                    areg[2] = Wc[(kk + tig + 4) * WSTR + mcol];
                    areg[3] = Wc[(kk + tig + 4) * WSTR + mcol + 8];
#pragma unroll
                    for (int nt = 0; nt < 4; nt++)
                        mma16n8k8(dacc[mt][nt], areg, breg[nt]);
                }
            }
            __syncthreads();
        }

        // write q/k/v fragments -> Rb/Rc/Rd [192][68] (Xb dead, chunk bufs dead)
#pragma unroll
        for (int mt = 0; mt < 5; mt++) {
#pragma unroll
            for (int half = 0; half < 2; half++) {
                int o = mg * 80 + mt * 16 + gid + half * 8;
                if (o < TDIM) {
                    int s = o / DIM, ch = o - s * DIM;
                    float* dst = (s == 0 ? Rb : s == 1 ? Rc : Rd) + ch * STRC + ng * 32 + 2 * tig;
#pragma unroll
                    for (int nt = 0; nt < 4; nt++)
                        *(float2*)(dst + nt * 8) =
                            make_float2(dacc[mt][nt][half * 2], dacc[mt][nt][half * 2 + 1]);
                }
            }
        }
    }
    __syncthreads();

    // ---- dwconv Q,V in place; K -> transposed Kt in Ra ----
    {
#pragma unroll
        for (int it = 0; it < 6; it++) {
            int t = it * NTHR + tid;
            int ch_ = t >> 3, row = t & 7;
            int isQ = ch_ < DIM;
            float* rr = (isQ ? Rb : Rd) + (isQ ? ch_ : ch_ - DIM) * STRC;
            int dwc = isQ ? ch_ : ch_ + DIM;
            const float* wd = dw_w + (size_t)dwc * 9;
            float w0 = __ldg(wd+0), w1 = __ldg(wd+1), w2 = __ldg(wd+2);
            float w3 = __ldg(wd+3), w4 = __ldg(wd+4), w5 = __ldg(wd+5);
            float w6 = __ldg(wd+6), w7 = __ldg(wd+7), w8 = __ldg(wd+8);
            float A[8], B[8], C[8];
            {
                const float4* r4 = (const float4*)(rr + row * 8);
                float4 b0 = r4[0], b1 = r4[1];
                B[0]=b0.x; B[1]=b0.y; B[2]=b0.z; B[3]=b0.w;
                B[4]=b1.x; B[5]=b1.y; B[6]=b1.z; B[7]=b1.w;
            }
            if (row > 0) {
                const float4* r4 = (const float4*)(rr + (row - 1) * 8);
                float4 a0 = r4[0], a1 = r4[1];
                A[0]=a0.x; A[1]=a0.y; A[2]=a0.z; A[3]=a0.w;
                A[4]=a1.x; A[5]=a1.y; A[6]=a1.z; A[7]=a1.w;
            } else {
#pragma unroll
                for (int j = 0; j < 8; j++) A[j] = 0.f;
            }
            if (row < 7) {
                const float4* r4 = (const float4*)(rr + (row + 1) * 8);
                float4 c0 = r4[0], c1 = r4[1];
                C[0]=c0.x; C[1]=c0.y; C[2]=c0.z; C[3]=c0.w;
                C[4]=c1.x; C[5]=c1.y; C[6]=c1.z; C[7]=c1.w;
            } else {
#pragma unroll
                for (int j = 0; j < 8; j++) C[j] = 0.f;
            }
            float o[8];
            float ss = 0.f;
#pragma unroll
            for (int j = 0; j < 8; j++) {
                float s = w1 * A[j] + w4 * B[j] + w7 * C[j];
                if (j > 0) s += w0 * A[j-1] + w3 * B[j-1] + w6 * C[j-1];
                if (j < 7) s += w2 * A[j+1] + w5 * B[j+1] + w8 * C[j+1];
                o[j] = s;
                ss += s * s;
            }
            ss += __shfl_xor_sync(0xffffffffu, ss, 4);
            ss += __shfl_xor_sync(0xffffffffu, ss, 2);
            ss += __shfl_xor_sync(0xffffffffu, ss, 1);
            __syncwarp();
            float4* w4p = (float4*)(rr + row * 8);
            w4p[0] = make_float4(o[0], o[1], o[2], o[3]);
            w4p[1] = make_float4(o[4], o[5], o[6], o[7]);
            if (isQ && (lane & 7) == 0)
                Ns[ch_] = 1.f / fmaxf(sqrtf(ss), 1e-12f);
            __syncwarp();
        }
#pragma unroll
        for (int it = 0; it < 3; it++) {
            int task = it * NTHR + tid;
            int ch = task % DIM;
            int row = task / DIM;
            const float* rr = Rc + ch * STRC;
            const float* wd = dw_w + (size_t)(DIM + ch) * 9;
            float w0 = __ldg(wd+0), w1 = __ldg(wd+1), w2 = __ldg(wd+2);
            float w3 = __ldg(wd+3), w4 = __ldg(wd+4), w5 = __ldg(wd+5);
            float w6 = __ldg(wd+6), w7 = __ldg(wd+7), w8 = __ldg(wd+8);
            float A[8], B[8], C[8];
            {
                const float4* r4 = (const float4*)(rr + row * 8);
                float4 b0 = r4[0], b1 = r4[1];
                B[0]=b0.x; B[1]=b0.y; B[2]=b0.z; B[3]=b0.w;
                B[4]=b1.x; B[5]=b1.y; B[6]=b1.z; B[7]=b1.w;
            }
            if (row > 0) {
                const float4* r4 = (const float4*)(rr + (row - 1) * 8);
                float4 a0 = r4[0], a1 = r4[1];
                A[0]=a0.x; A[1]=a0.y; A[2]=a0.z; A[3]=a0.w;
                A[4]=a1.x; A[5]=a1.y; A[6]=a1.z; A[7]=a1.w;
            } else {
#pragma unroll
                for (int j = 0; j < 8; j++) A[j] = 0.f;
            }
            if (row < 7) {
                const float4* r4 = (const float4*)(rr + (row + 1) * 8);
                float4 c0 = r4[0], c1 = r4[1];
                C[0]=c0.x; C[1]=c0.y; C[2]=c0.z; C[3]=c0.w;
                C[4]=c1.x; C[5]=c1.y; C[6]=c1.z; C[7]=c1.w;
            } else {
#pragma unroll
                for (int j = 0; j < 8; j++) C[j] = 0.f;
            }
            float ss = 0.f;
#pragma unroll
            for (int j = 0; j < 8; j++) {
                float s = w1 * A[j] + w4 * B[j] + w7 * C[j];
                if (j > 0) s += w0 * A[j-1] + w3 * B[j-1] + w6 * C[j-1];
                if (j < 7) s += w2 * A[j+1] + w5 * B[j+1] + w8 * C[j+1];
                Ra[(row * 8 + j) * STRK + ch] = s;
                ss += s * s;
            }
            atomicAdd(&Ns[DIM + ch], ss);
        }
    }
    __syncthreads();

    if (tid < DIM) Ns[DIM + tid] = 1.f / fmaxf(sqrtf(Ns[DIM + tid]), 1e-12f);
    __syncthreads();

    // ---- scores: Q (Rb) x Kt (Ra) -> As (Rc) ----
    {
        float* As = Rc;
        const int rgr = tid >> 3;
        const int kg = tid & 7;
        int rows[3] = {rgr, rgr + 64, rgr + 128};
        ull acc[3][2];
#pragma unroll
        for (int j = 0; j < 3; j++) { acc[j][0] = 0ull; acc[j][1] = 0ull; }
        int kc[3];
#pragma unroll
        for (int j = 0; j < 3; j++) kc[j] = (rows[j] & ~31) + kg * 4;
#pragma unroll 4
        for (int p = 0; p < 64; p++) {
            const float* ktp = Ra + p * STRK;
#pragma unroll
            for (int j = 0; j < 3; j++) {
                ull qd = dup2(Rb[rows[j] * STRC + p]);
                const ull* kv = (const ull*)(ktp + kc[j]);
                ffma2(acc[j][0], kv[0], qd);
                ffma2(acc[j][1], kv[1], qd);
            }
        }
#pragma unroll
        for (int j = 0; j < 3; j++) {
            int row = rows[j];
            float tmp = __ldg(temperature + (row >> 5));
            float invq = Ns[row] * tmp;
            float2 f0 = ull2f2(acc[j][0]), f1 = ull2f2(acc[j][1]);
            float* arow = As + row * STRA + kg * 4;
            arow[0] = f0.x * invq * Ns[DIM + kc[j]];
            arow[1] = f0.y * invq * Ns[DIM + kc[j] + 1];
            arow[2] = f1.x * invq * Ns[DIM + kc[j] + 2];
            arow[3] = f1.y * invq * Ns[DIM + kc[j] + 3];
        }
    }
    __syncthreads();

    // ---- softmax ----
    if (tid < DIM) {
        float* arow = Rc + tid * STRA;
        float m = arow[0];
#pragma unroll
        for (int d = 1; d < 32; d++) m = fmaxf(m, arow[d]);
        float s = 0.f;
#pragma unroll
        for (int d = 0; d < 32; d++) { float e = expf(arow[d] - m); arow[d] = e; s += e; }
        float inv = 1.f / s;
#pragma unroll
        for (int d = 0; d < 32; d++) arow[d] *= inv;
    }
    __syncthreads();

    // ---- out = attn @ v -> Ra [192][64] ----
    {
        ull acc2[6][2];
#pragma unroll
        for (int r = 0; r < 6; r++) { acc2[r][0] = 0ull; acc2[r][1] = 0ull; }
        const ull* v8 = (const ull*)Rd;
        const float* As = Rc;
        for (int d = 0; d < 32; d++) {
#pragma unroll
            for (int r = 0; r < 6; r++) {
                int row = rg * 6 + r;
                int base = row & ~31;
                ull ad = dup2(As[row * STRA + d]);
                int vb = (base + d) * (STRC / 2) + cg * 2;
                ffma2(acc2[r][0], v8[vb], ad);
                ffma2(acc2[r][1], v8[vb + 1], ad);
            }
        }
        float4* o4 = (float4*)Ra;
#pragma unroll
        for (int r = 0; r < 6; r++) {
            float2 a = ull2f2(acc2[r][0]), b = ull2f2(acc2[r][1]);
            o4[(rg * 6 + r) * 16 + cg] = make_float4(a.x, a.y, b.x, b.y);
        }
    }
    __syncthreads();

    // ---- proj GEMM, double-buffered staging in Rc ----
    {
        float* P0 = Rc;
        float* P1 = Rc + 6144;
        ull acc[3][4];
#pragma unroll
        for (int p = 0; p < 3; p++)
#pragma unroll
            for (int j = 0; j < 4; j++) acc[p][j] = 0ull;
        const float4* s4 = (const float4*)Ra;
        const float4* gp = (const float4*)g_projT;
        {
            float4* dst = (float4*)P0;
            for (int e = tid; e < 1536; e += NTHR) dst[e] = __ldg(gp + e);
        }
        __syncthreads();
        for (int kt = 0; kt < 6; kt++) {
            const float* Pcur = (kt & 1) ? P1 : P0;
            if (kt < 5) {
                float4* dst = (float4*)((kt & 1) ? P0 : P1);
                const float4* src = gp + (kt + 1) * 1536;
                for (int e = tid; e < 1536; e += NTHR) dst[e] = __ldg(src + e);
            }
#pragma unroll 4
            for (int cl = 0; cl < 32; cl++) {
                int c = kt * 32 + cl;
                float4 xv = s4[c * 16 + cg];
                ull xd0 = dup2(xv.x), xd1 = dup2(xv.y), xd2 = dup2(xv.z), xd3 = dup2(xv.w);
                const ull* wrow = (const ull*)(Pcur + cl * DIM + rg * 6);
                ull w0 = wrow[0], w1 = wrow[1], w2 = wrow[2];
                ffma2(acc[0][0], w0, xd0); ffma2(acc[1][0], w1, xd0); ffma2(acc[2][0], w2, xd0);
                ffma2(acc[0][1], w0, xd1); ffma2(acc[1][1], w1, xd1); ffma2(acc[2][1], w2, xd1);
                ffma2(acc[0][2], w0, xd2); ffma2(acc[1][2], w1, xd2); ffma2(acc[2][2], w2, xd2);
                ffma2(acc[0][3], w0, xd3); ffma2(acc[1][3], w1, xd3); ffma2(acc[2][3], w2, xd3);
            }
            __syncthreads();
        }
        int gh = (wh * WSZ + (cg >> 1) + SHIFTV) & 255;
#pragma unroll
        for (int p = 0; p < 3; p++) {
            float2 f0 = ull2f2(acc[p][0]), f1 = ull2f2(acc[p][1]);
            float2 f2 = ull2f2(acc[p][2]), f3 = ull2f2(acc[p][3]);
            float v0[4] = {f0.x, f1.x, f2.x, f3.x};
            float v1[4] = {f0.y, f1.y, f2.y, f3.y};
            int o0 = rg * 6 + 2 * p;
            float* orow0 = out + ((size_t)(bi * DIM + o0) * IMG + gh) * IMG;
            float* orow1 = out + ((size_t)(bi * DIM + o0 + 1) * IMG + gh) * IMG;
#pragma unroll
            for (int u = 0; u < 4; u++) {
                int j = ((cg & 1) * 4 + u);
                int gw = (ww * WSZ + j + SHIFTV) & 255;
                orow0[gw] = v0[u];
                orow1[gw] = v1[u];
            }
        }
    }
}

extern "C" void kernel_launch(void* const* d_in, const int* in_sizes, int n_in,
                              void* d_out, int out_size) {
    const float* x           = (const float*)d_in[0];
    const float* qkv_w       = (const float*)d_in[1];
    const float* dw_w        = (const float*)d_in[2];
    const float* proj_w      = (const float*)d_in[3];
    const float* temperature = (const float*)d_in[4];
    float* out = (float*)d_out;

    cudaFuncSetAttribute(attn_kernel, cudaFuncAttributeMaxDynamicSharedMemorySize,
                         SMEM_FLOATS * 4);
    wtrans_kernel<<<(DIM * 640 + 255) / 256, 256>>>(qkv_w, proj_w);
    attn_kernel<<<4096, NTHR, SMEM_FLOATS * 4>>>(x, dw_w, temperature, out);
}

// round 11
// speedup vs baseline: 2.4251x; 1.1726x over previous
#include <cuda_runtime.h>
#include <cstdint>

#define DIM   192
#define TDIM  576
#define WSZ   8
#define PIX   64
#define IMG   256
#define SHIFTV 4
#define NTHR  512

#define STRC  68
#define STRK  196
#define STRA  33
#define WSTR  648     // qkv staged chunk col stride
#define PSTR  200     // proj staged chunk col stride (==8 mod 32: conflict-free)

#define A_OFF  0      // Ws0 chunk -> Kt[64][196] -> proj weight chunks
#define B_OFF  12544  // Xb tf32 [192][68] -> Q [192][68] -> attn-out tf32 [192][68]
#define C_OFF  25600  // Ws1 chunk -> rawK [192][68] -> As[192][33]
#define D_OFF  38656  // rawV/V [192][68]
#define NS_OFF 51712
#define SMEM_FLOATS 52160

typedef unsigned long long ull;

__device__ uint32_t g_qkvK[DIM * 640];    // k-major tf32: [c][o], o>=576 zero
__device__ uint32_t g_projK[DIM * DIM];   // k-major tf32: [c][o]

__device__ __forceinline__ uint32_t f2tf32(float f) {
    uint32_t u; asm("cvt.rna.tf32.f32 %0, %1;" : "=r"(u) : "f"(f)); return u;
}

__global__ void wtrans_kernel(const float* __restrict__ qkv_w,
                              const float* __restrict__ proj_w) {
    int i = blockIdx.x * 256 + threadIdx.x;
    if (i < DIM * 640) {
        int c = i / 640, o = i % 640;
        g_qkvK[i] = (o < TDIM) ? f2tf32(qkv_w[o * DIM + c]) : 0u;
    }
    if (i < DIM * DIM) {
        int c = i / DIM, o = i % DIM;
        g_projK[i] = f2tf32(proj_w[o * DIM + c]);
    }
}

__device__ __forceinline__ ull dup2(float v) {
    ull r; asm("mov.b64 %0, {%1, %1};" : "=l"(r) : "f"(v)); return r;
}
__device__ __forceinline__ void ffma2(ull& d, ull a, ull b) {
    asm("fma.rn.f32x2 %0, %1, %2, %0;" : "+l"(d) : "l"(a), "l"(b));
}
__device__ __forceinline__ float2 ull2f2(ull v) {
    float2 r; asm("mov.b64 {%0, %1}, %2;" : "=f"(r.x), "=f"(r.y) : "l"(v)); return r;
}
__device__ __forceinline__ void mma16n8k8(float* d, const uint32_t* a, const uint32_t* b) {
    asm volatile(
        "mma.sync.aligned.m16n8k8.row.col.f32.tf32.tf32.f32 "
        "{%0,%1,%2,%3}, {%4,%5,%6,%7}, {%8,%9}, {%0,%1,%2,%3};"
        : "+f"(d[0]), "+f"(d[1]), "+f"(d[2]), "+f"(d[3])
        : "r"(a[0]), "r"(a[1]), "r"(a[2]), "r"(a[3]), "r"(b[0]), "r"(b[1]));
}

__global__ void __launch_bounds__(NTHR, 1)
attn_kernel(const float* __restrict__ x, const float* __restrict__ dw_w,
            const float* __restrict__ temperature, float* __restrict__ out) {
    extern __shared__ float sm[];
    float* Ra = sm + A_OFF;
    float* Rb = sm + B_OFF;
    float* Rc = sm + C_OFF;
    float* Rd = sm + D_OFF;
    float* Ns = sm + NS_OFF;

    const int tid = threadIdx.x;
    const int win = blockIdx.x;
    const int bi = win >> 10;
    const int wh = (win >> 5) & 31;
    const int ww = win & 31;
    const int rg = tid >> 4;
    const int cg = tid & 15;
    const int lane = tid & 31;
    const int wid = tid >> 5;

    if (tid < DIM) Ns[DIM + tid] = 0.f;

    // ---- load window with roll(-4,-4) into Rb as tf32 bits [192][68] ----
    {
        const float* xb = x + (size_t)bi * DIM * IMG * IMG;
        uint32_t* Xu = (uint32_t*)Rb;
        for (int e = tid; e < DIM * PIX; e += NTHR) {
            int c = e >> 6, p = e & 63;
            int i = p >> 3, j = p & 7;
            int gh = (wh * WSZ + i + SHIFTV) & 255;
            int gw = (ww * WSZ + j + SHIFTV) & 255;
            Xu[c * STRC + p] = f2tf32(xb[(c * IMG + gh) * IMG + gw]);
        }
    }

    // ---- qkv GEMM via mma.sync tf32 ----
    {
        const uint32_t* Xu = (const uint32_t*)Rb;
        const int gid = lane >> 2, tig = lane & 3;
        const int mg = wid >> 1, ng = wid & 1;
        float dacc[5][4][4];
#pragma unroll
        for (int mt = 0; mt < 5; mt++)
#pragma unroll
            for (int nt = 0; nt < 4; nt++)
#pragma unroll
                for (int q = 0; q < 4; q++) dacc[mt][nt][q] = 0.f;

        {
            const uint4* src = (const uint4*)g_qkvK;
            for (int e = tid; e < 2560; e += NTHR) {
                int r = e / 160, c4 = e - r * 160;
                ((uint4*)((uint32_t*)Ra + r * WSTR))[c4] = __ldg(src + e);
            }
        }
        __syncthreads();

        for (int kc = 0; kc < 12; kc++) {
            const uint32_t* Wc = (const uint32_t*)((kc & 1) ? Rc : Ra);
            if (kc < 11) {
                uint32_t* Wn = (uint32_t*)((kc & 1) ? Ra : Rc);
                const uint4* src = (const uint4*)(g_qkvK + (size_t)(kc + 1) * 16 * 640);
                for (int e = tid; e < 2560; e += NTHR) {
                    int r = e / 160, c4 = e - r * 160;
                    ((uint4*)(Wn + r * WSTR))[c4] = __ldg(src + e);
                }
            }
#pragma unroll
            for (int ks = 0; ks < 2; ks++) {
                const int kk = ks * 8;
                uint32_t breg[4][2];
#pragma unroll
                for (int nt = 0; nt < 4; nt++) {
                    int col = ng * 32 + nt * 8 + gid;
                    breg[nt][0] = Xu[(kc * 16 + kk + tig) * STRC + col];
                    breg[nt][1] = Xu[(kc * 16 + kk + tig + 4) * STRC + col];
                }
#pragma unroll
                for (int mt = 0; mt < 5; mt++) {
                    int mcol = mg * 80 + mt * 16 + gid;
                    uint32_t areg[4];
                    areg[0] = Wc[(kk + tig) * WSTR + mcol];
                    areg[1] = Wc[(kk + tig) * WSTR + mcol + 8];
                    areg[2] = Wc[(kk + tig + 4) * WSTR + mcol];
                    areg[3] = Wc[(kk + tig + 4) * WSTR + mcol + 8];
#pragma unroll
                    for (int nt = 0; nt < 4; nt++)
                        mma16n8k8(dacc[mt][nt], areg, breg[nt]);
                }
            }
            __syncthreads();
        }

#pragma unroll
        for (int mt = 0; mt < 5; mt++) {
#pragma unroll
            for (int half = 0; half < 2; half++) {
                int o = mg * 80 + mt * 16 + gid + half * 8;
                if (o < TDIM) {
                    int s = o / DIM, ch = o - s * DIM;
                    float* dst = (s == 0 ? Rb : s == 1 ? Rc : Rd) + ch * STRC + ng * 32 + 2 * tig;
#pragma unroll
                    for (int nt = 0; nt < 4; nt++)
                        *(float2*)(dst + nt * 8) =
                            make_float2(dacc[mt][nt][half * 2], dacc[mt][nt][half * 2 + 1]);
                }
            }
        }
    }
    __syncthreads();

    // ---- dwconv Q,V in place; K -> transposed Kt in Ra ----
    {
#pragma unroll
        for (int it = 0; it < 6; it++) {
            int t = it * NTHR + tid;
            int ch_ = t >> 3, row = t & 7;
            int isQ = ch_ < DIM;
            float* rr = (isQ ? Rb : Rd) + (isQ ? ch_ : ch_ - DIM) * STRC;
            int dwc = isQ ? ch_ : ch_ + DIM;
            const float* wd = dw_w + (size_t)dwc * 9;
            float w0 = __ldg(wd+0), w1 = __ldg(wd+1), w2 = __ldg(wd+2);
            float w3 = __ldg(wd+3), w4 = __ldg(wd+4), w5 = __ldg(wd+5);
            float w6 = __ldg(wd+6), w7 = __ldg(wd+7), w8 = __ldg(wd+8);
            float A[8], B[8], C[8];
            {
                const float4* r4 = (const float4*)(rr + row * 8);
                float4 b0 = r4[0], b1 = r4[1];
                B[0]=b0.x; B[1]=b0.y; B[2]=b0.z; B[3]=b0.w;
                B[4]=b1.x; B[5]=b1.y; B[6]=b1.z; B[7]=b1.w;
            }
            if (row > 0) {
                const float4* r4 = (const float4*)(rr + (row - 1) * 8);
                float4 a0 = r4[0], a1 = r4[1];
                A[0]=a0.x; A[1]=a0.y; A[2]=a0.z; A[3]=a0.w;
                A[4]=a1.x; A[5]=a1.y; A[6]=a1.z; A[7]=a1.w;
            } else {
#pragma unroll
                for (int j = 0; j < 8; j++) A[j] = 0.f;
            }
            if (row < 7) {
                const float4* r4 = (const float4*)(rr + (row + 1) * 8);
                float4 c0 = r4[0], c1 = r4[1];
                C[0]=c0.x; C[1]=c0.y; C[2]=c0.z; C[3]=c0.w;
                C[4]=c1.x; C[5]=c1.y; C[6]=c1.z; C[7]=c1.w;
            } else {
#pragma unroll
                for (int j = 0; j < 8; j++) C[j] = 0.f;
            }
            float o[8];
            float ss = 0.f;
#pragma unroll
            for (int j = 0; j < 8; j++) {
                float s = w1 * A[j] + w4 * B[j] + w7 * C[j];
                if (j > 0) s += w0 * A[j-1] + w3 * B[j-1] + w6 * C[j-1];
                if (j < 7) s += w2 * A[j+1] + w5 * B[j+1] + w8 * C[j+1];
                o[j] = s;
                ss += s * s;
            }
            ss += __shfl_xor_sync(0xffffffffu, ss, 4);
            ss += __shfl_xor_sync(0xffffffffu, ss, 2);
            ss += __shfl_xor_sync(0xffffffffu, ss, 1);
            __syncwarp();
            float4* w4p = (float4*)(rr + row * 8);
            w4p[0] = make_float4(o[0], o[1], o[2], o[3]);
            w4p[1] = make_float4(o[4], o[5], o[6], o[7]);
            if (isQ && (lane & 7) == 0)
                Ns[ch_] = 1.f / fmaxf(sqrtf(ss), 1e-12f);
            __syncwarp();
        }
#pragma unroll
        for (int it = 0; it < 3; it++) {
            int task = it * NTHR + tid;
            int ch = task % DIM;
            int row = task / DIM;
            const float* rr = Rc + ch * STRC;
            const float* wd = dw_w + (size_t)(DIM + ch) * 9;
            float w0 = __ldg(wd+0), w1 = __ldg(wd+1), w2 = __ldg(wd+2);
            float w3 = __ldg(wd+3), w4 = __ldg(wd+4), w5 = __ldg(wd+5);
            float w6 = __ldg(wd+6), w7 = __ldg(wd+7), w8 = __ldg(wd+8);
            float A[8], B[8], C[8];
            {
                const float4* r4 = (const float4*)(rr + row * 8);
                float4 b0 = r4[0], b1 = r4[1];
                B[0]=b0.x; B[1]=b0.y; B[2]=b0.z; B[3]=b0.w;
                B[4]=b1.x; B[5]=b1.y; B[6]=b1.z; B[7]=b1.w;
            }
            if (row > 0) {
                const float4* r4 = (const float4*)(rr + (row - 1) * 8);
                float4 a0 = r4[0], a1 = r4[1];
                A[0]=a0.x; A[1]=a0.y; A[2]=a0.z; A[3]=a0.w;
                A[4]=a1.x; A[5]=a1.y; A[6]=a1.z; A[7]=a1.w;
            } else {
#pragma unroll
                for (int j = 0; j < 8; j++) A[j] = 0.f;
            }
            if (row < 7) {
                const float4* r4 = (const float4*)(rr + (row + 1) * 8);
                float4 c0 = r4[0], c1 = r4[1];
                C[0]=c0.x; C[1]=c0.y; C[2]=c0.z; C[3]=c0.w;
                C[4]=c1.x; C[5]=c1.y; C[6]=c1.z; C[7]=c1.w;
            } else {
#pragma unroll
                for (int j = 0; j < 8; j++) C[j] = 0.f;
            }
            float ss = 0.f;
#pragma unroll
            for (int j = 0; j < 8; j++) {
                float s = w1 * A[j] + w4 * B[j] + w7 * C[j];
                if (j > 0) s += w0 * A[j-1] + w3 * B[j-1] + w6 * C[j-1];
                if (j < 7) s += w2 * A[j+1] + w5 * B[j+1] + w8 * C[j+1];
                Ra[(row * 8 + j) * STRK + ch] = s;
                ss += s * s;
            }
            atomicAdd(&Ns[DIM + ch], ss);
        }
    }
    __syncthreads();

    if (tid < DIM) Ns[DIM + tid] = 1.f / fmaxf(sqrtf(Ns[DIM + tid]), 1e-12f);
    __syncthreads();

    // ---- scores: Q (Rb) x Kt (Ra) -> As (Rc) ----
    {
        float* As = Rc;
        const int rgr = tid >> 3;
        const int kg = tid & 7;
        int rows[3] = {rgr, rgr + 64, rgr + 128};
        ull acc[3][2];
#pragma unroll
        for (int j = 0; j < 3; j++) { acc[j][0] = 0ull; acc[j][1] = 0ull; }
        int kc[3];
#pragma unroll
        for (int j = 0; j < 3; j++) kc[j] = (rows[j] & ~31) + kg * 4;
#pragma unroll 4
        for (int p = 0; p < 64; p++) {
            const float* ktp = Ra + p * STRK;
#pragma unroll
            for (int j = 0; j < 3; j++) {
                ull qd = dup2(Rb[rows[j] * STRC + p]);
                const ull* kv = (const ull*)(ktp + kc[j]);
                ffma2(acc[j][0], kv[0], qd);
                ffma2(acc[j][1], kv[1], qd);
            }
        }
#pragma unroll
        for (int j = 0; j < 3; j++) {
            int row = rows[j];
            float tmp = __ldg(temperature + (row >> 5));
            float invq = Ns[row] * tmp;
            float2 f0 = ull2f2(acc[j][0]), f1 = ull2f2(acc[j][1]);
            float* arow = As + row * STRA + kg * 4;
            arow[0] = f0.x * invq * Ns[DIM + kc[j]];
            arow[1] = f0.y * invq * Ns[DIM + kc[j] + 1];
            arow[2] = f1.x * invq * Ns[DIM + kc[j] + 2];
            arow[3] = f1.y * invq * Ns[DIM + kc[j] + 3];
        }
    }
    __syncthreads();

    // ---- softmax ----
    if (tid < DIM) {
        float* arow = Rc + tid * STRA;
        float m = arow[0];
#pragma unroll
        for (int d = 1; d < 32; d++) m = fmaxf(m, arow[d]);
        float s = 0.f;
#pragma unroll
        for (int d = 0; d < 32; d++) { float e = expf(arow[d] - m); arow[d] = e; s += e; }
        float inv = 1.f / s;
#pragma unroll
        for (int d = 0; d < 32; d++) arow[d] *= inv;
    }
    __syncthreads();

    // ---- out = attn @ v -> Rb as tf32 [192][68] (Q dead) ----
    {
        ull acc2[6][2];
#pragma unroll
        for (int r = 0; r < 6; r++) { acc2[r][0] = 0ull; acc2[r][1] = 0ull; }
        const ull* v8 = (const ull*)Rd;
        const float* As = Rc;
        for (int d = 0; d < 32; d++) {
#pragma unroll
            for (int r = 0; r < 6; r++) {
                int row = rg * 6 + r;
                int base = row & ~31;
                ull ad = dup2(As[row * STRA + d]);
                int vb = (base + d) * (STRC / 2) + cg * 2;
                ffma2(acc2[r][0], v8[vb], ad);
                ffma2(acc2[r][1], v8[vb + 1], ad);
            }
        }
        __syncthreads();
        uint32_t* Ou = (uint32_t*)Rb;
#pragma unroll
        for (int r = 0; r < 6; r++) {
            float2 a = ull2f2(acc2[r][0]), b = ull2f2(acc2[r][1]);
            uint4 t;
            t.x = f2tf32(a.x); t.y = f2tf32(a.y); t.z = f2tf32(b.x); t.w = f2tf32(b.y);
            *(uint4*)(Ou + (rg * 6 + r) * STRC + cg * 4) = t;
        }
    }
    __syncthreads();

    // ---- proj GEMM via mma.sync tf32, weights staged in Ra (16-k chunks) ----
    {
        const uint32_t* Xu = (const uint32_t*)Rb;
        const int gid = lane >> 2, tig = lane & 3;
        const int mgr = wid >> 2, ngr = wid & 3;   // 4 m-groups x 4 n-groups
        float dacc[3][2][4];
#pragma unroll
        for (int mt = 0; mt < 3; mt++)
#pragma unroll
            for (int nt = 0; nt < 2; nt++)
#pragma unroll
                for (int q = 0; q < 4; q++) dacc[mt][nt][q] = 0.f;

        {
            const uint4* src = (const uint4*)g_projK;
            for (int e = tid; e < 768; e += NTHR) {
                int r = e / 48, c4 = e - r * 48;
                ((uint4*)((uint32_t*)Ra + r * PSTR))[c4] = __ldg(src + e);
            }
        }
        __syncthreads();

        for (int kc = 0; kc < 12; kc++) {
            const uint32_t* Wc = (const uint32_t*)Ra + (kc & 1) * 3200;
            if (kc < 11) {
                uint32_t* Wn = (uint32_t*)Ra + ((kc + 1) & 1) * 3200;
                const uint4* src = (const uint4*)(g_projK + (size_t)(kc + 1) * 16 * DIM);
                for (int e = tid; e < 768; e += NTHR) {
                    int r = e / 48, c4 = e - r * 48;
                    ((uint4*)(Wn + r * PSTR))[c4] = __ldg(src + e);
                }
            }
#pragma unroll
            for (int ks = 0; ks < 2; ks++) {
                const int kk = ks * 8;
                uint32_t breg[2][2];
#pragma unroll
                for (int nt = 0; nt < 2; nt++) {
                    int col = ngr * 16 + nt * 8 + gid;
                    breg[nt][0] = Xu[(kc * 16 + kk + tig) * STRC + col];
                    breg[nt][1] = Xu[(kc * 16 + kk + tig + 4) * STRC + col];
                }
#pragma unroll
                for (int mt = 0; mt < 3; mt++) {
                    int mcol = mgr * 48 + mt * 16 + gid;
                    uint32_t areg[4];
                    areg[0] = Wc[(kk + tig) * PSTR + mcol];
                    areg[1] = Wc[(kk + tig) * PSTR + mcol + 8];
                    areg[2] = Wc[(kk + tig + 4) * PSTR + mcol];
                    areg[3] = Wc[(kk + tig + 4) * PSTR + mcol + 8];
#pragma unroll
                    for (int nt = 0; nt < 2; nt++)
                        mma16n8k8(dacc[mt][nt], areg, breg[nt]);
                }
            }
            __syncthreads();
        }

        // epilogue: fragments -> gmem with roll(+4,+4)
#pragma unroll
        for (int mt = 0; mt < 3; mt++) {
#pragma unroll
            for (int half = 0; half < 2; half++) {
                int o = mgr * 48 + mt * 16 + gid + half * 8;
                float* obase = out + ((size_t)(bi * DIM + o) * IMG) * IMG;
#pragma unroll
                for (int nt = 0; nt < 2; nt++) {
                    int p = ngr * 16 + nt * 8 + 2 * tig;
                    int i = p >> 3, j = p & 7;
                    int gh = (wh * WSZ + i + SHIFTV) & 255;
                    int gw0 = (ww * WSZ + j + SHIFTV) & 255;
                    int gw1 = (ww * WSZ + j + 1 + SHIFTV) & 255;
                    obase[gh * IMG + gw0] = dacc[mt][nt][half * 2];
                    obase[gh * IMG + gw1] = dacc[mt][nt][half * 2 + 1];
                }
            }
        }
    }
}

extern "C" void kernel_launch(void* const* d_in, const int* in_sizes, int n_in,
                              void* d_out, int out_size) {
    const float* x           = (const float*)d_in[0];
    const float* qkv_w       = (const float*)d_in[1];
    const float* dw_w        = (const float*)d_in[2];
    const float* proj_w      = (const float*)d_in[3];
    const float* temperature = (const float*)d_in[4];
    float* out = (float*)d_out;

    cudaFuncSetAttribute(attn_kernel, cudaFuncAttributeMaxDynamicSharedMemorySize,
                         SMEM_FLOATS * 4);
    wtrans_kernel<<<(DIM * 640 + 255) / 256, 256>>>(qkv_w, proj_w);
    attn_kernel<<<4096, NTHR, SMEM_FLOATS * 4>>>(x, dw_w, temperature, out);
}

// round 12
// speedup vs baseline: 2.8658x; 1.1817x over previous
#include <cuda_runtime.h>
#include <cstdint>

#define DIM   192
#define TDIM  576
#define WSZ   8
#define PIX   64
#define IMG   256
#define SHIFTV 4
#define NTHR  512

#define STRC  68
#define STRK  196
#define STRA  33
#define WSTR  648     // qkv staged chunk col stride
#define PSTR  200     // proj staged chunk col stride

#define A_OFF  0      // qkv Ws0 chunk -> Vt[64][196] tf32 -> proj weight chunks
#define B_OFF  12544  // Xb tf32 [192][68] -> Q tf32 [192][68] -> attn-out tf32 [192][68]
#define C_OFF  25600  // qkv Ws1 chunk -> K tf32 [192][68]
#define D_OFF  38656  // rawV [192][68] -> As [192][33]
#define NS_OFF 51712  // Ns[0..191] q-norms, [192..383] k-norms
#define SMEM_FLOATS 52160

typedef unsigned long long ull;

__device__ uint32_t g_qkvK[DIM * 640];    // k-major tf32: [c][o], o>=576 zero
__device__ uint32_t g_projK[DIM * DIM];   // k-major tf32: [c][o]

__device__ __forceinline__ uint32_t f2tf32(float f) {
    uint32_t u; asm("cvt.rna.tf32.f32 %0, %1;" : "=r"(u) : "f"(f)); return u;
}

__global__ void wtrans_kernel(const float* __restrict__ qkv_w,
                              const float* __restrict__ proj_w) {
    int i = blockIdx.x * 256 + threadIdx.x;
    if (i < DIM * 640) {
        int c = i / 640, o = i % 640;
        g_qkvK[i] = (o < TDIM) ? f2tf32(qkv_w[o * DIM + c]) : 0u;
    }
    if (i < DIM * DIM) {
        int c = i / DIM, o = i % DIM;
        g_projK[i] = f2tf32(proj_w[o * DIM + c]);
    }
}

__device__ __forceinline__ void mma16n8k8(float* d, const uint32_t* a, const uint32_t* b) {
    asm volatile(
        "mma.sync.aligned.m16n8k8.row.col.f32.tf32.tf32.f32 "
        "{%0,%1,%2,%3}, {%4,%5,%6,%7}, {%8,%9}, {%0,%1,%2,%3};"
        : "+f"(d[0]), "+f"(d[1]), "+f"(d[2]), "+f"(d[3])
        : "r"(a[0]), "r"(a[1]), "r"(a[2]), "r"(a[3]), "r"(b[0]), "r"(b[1]));
}

__global__ void __launch_bounds__(NTHR, 1)
attn_kernel(const float* __restrict__ x, const float* __restrict__ dw_w,
            const float* __restrict__ temperature, float* __restrict__ out) {
    extern __shared__ float sm[];
    float* Ra = sm + A_OFF;
    float* Rb = sm + B_OFF;
    float* Rc = sm + C_OFF;
    float* Rd = sm + D_OFF;
    float* Ns = sm + NS_OFF;

    const int tid = threadIdx.x;
    const int win = blockIdx.x;
    const int bi = win >> 10;
    const int wh = (win >> 5) & 31;
    const int ww = win & 31;
    const int lane = tid & 31;
    const int wid = tid >> 5;

    // ---- load window with roll(-4,-4) into Rb as tf32 bits [192][68] ----
    {
        const float* xb = x + (size_t)bi * DIM * IMG * IMG;
        uint32_t* Xu = (uint32_t*)Rb;
        for (int e = tid; e < DIM * PIX; e += NTHR) {
            int c = e >> 6, p = e & 63;
            int i = p >> 3, j = p & 7;
            int gh = (wh * WSZ + i + SHIFTV) & 255;
            int gw = (ww * WSZ + j + SHIFTV) & 255;
            Xu[c * STRC + p] = f2tf32(xb[(c * IMG + gh) * IMG + gw]);
        }
    }

    // ---- qkv GEMM via mma.sync tf32 ----
    {
        const uint32_t* Xu = (const uint32_t*)Rb;
        const int gid = lane >> 2, tig = lane & 3;
        const int mg = wid >> 1, ng = wid & 1;
        float dacc[5][4][4];
#pragma unroll
        for (int mt = 0; mt < 5; mt++)
#pragma unroll
            for (int nt = 0; nt < 4; nt++)
#pragma unroll
                for (int q = 0; q < 4; q++) dacc[mt][nt][q] = 0.f;

        {
            const uint4* src = (const uint4*)g_qkvK;
            for (int e = tid; e < 2560; e += NTHR) {
                int r = e / 160, c4 = e - r * 160;
                ((uint4*)((uint32_t*)Ra + r * WSTR))[c4] = __ldg(src + e);
            }
        }
        __syncthreads();

        for (int kc = 0; kc < 12; kc++) {
            const uint32_t* Wc = (const uint32_t*)((kc & 1) ? Rc : Ra);
            if (kc < 11) {
                uint32_t* Wn = (uint32_t*)((kc & 1) ? Ra : Rc);
                const uint4* src = (const uint4*)(g_qkvK + (size_t)(kc + 1) * 16 * 640);
                for (int e = tid; e < 2560; e += NTHR) {
                    int r = e / 160, c4 = e - r * 160;
                    ((uint4*)(Wn + r * WSTR))[c4] = __ldg(src + e);
                }
            }
#pragma unroll
            for (int ks = 0; ks < 2; ks++) {
                const int kk = ks * 8;
                uint32_t breg[4][2];
#pragma unroll
                for (int nt = 0; nt < 4; nt++) {
                    int col = ng * 32 + nt * 8 + gid;
                    breg[nt][0] = Xu[(kc * 16 + kk + tig) * STRC + col];
                    breg[nt][1] = Xu[(kc * 16 + kk + tig + 4) * STRC + col];
                }
#pragma unroll
                for (int mt = 0; mt < 5; mt++) {
                    int mcol = mg * 80 + mt * 16 + gid;
                    uint32_t areg[4];
                    areg[0] = Wc[(kk + tig) * WSTR + mcol];
                    areg[1] = Wc[(kk + tig) * WSTR + mcol + 8];
                    areg[2] = Wc[(kk + tig + 4) * WSTR + mcol];
                    areg[3] = Wc[(kk + tig + 4) * WSTR + mcol + 8];
#pragma unroll
                    for (int nt = 0; nt < 4; nt++)
                        mma16n8k8(dacc[mt][nt], areg, breg[nt]);
                }
            }
            __syncthreads();
        }

#pragma unroll
        for (int mt = 0; mt < 5; mt++) {
#pragma unroll
            for (int half = 0; half < 2; half++) {
                int o = mg * 80 + mt * 16 + gid + half * 8;
                if (o < TDIM) {
                    int s = o / DIM, ch = o - s * DIM;
                    float* dst = (s == 0 ? Rb : s == 1 ? Rc : Rd) + ch * STRC + ng * 32 + 2 * tig;
#pragma unroll
                    for (int nt = 0; nt < 4; nt++)
                        *(float2*)(dst + nt * 8) =
                            make_float2(dacc[mt][nt][half * 2], dacc[mt][nt][half * 2 + 1]);
                }
            }
        }
    }
    __syncthreads();

    // ---- dwconv: Q (Rb) and K (Rc) in place with norms; V (Rd) -> Vt (Ra) ----
    {
        // Q + K, in place, tf32-rounded stores, shuffle norms
#pragma unroll
        for (int it = 0; it < 6; it++) {
            int t = it * NTHR + tid;
            int ch_ = t >> 3, row = t & 7;      // ch_ 0..383: Q then K
            int isQ = ch_ < DIM;
            float* rr = (isQ ? Rb : Rc) + (isQ ? ch_ : ch_ - DIM) * STRC;
            const float* wd = dw_w + (size_t)ch_ * 9;   // dw channels: Q 0..191, K 192..383
            float w0 = __ldg(wd+0), w1 = __ldg(wd+1), w2 = __ldg(wd+2);
            float w3 = __ldg(wd+3), w4 = __ldg(wd+4), w5 = __ldg(wd+5);
            float w6 = __ldg(wd+6), w7 = __ldg(wd+7), w8 = __ldg(wd+8);
            float A[8], B[8], C[8];
            {
                const float4* r4 = (const float4*)(rr + row * 8);
                float4 b0 = r4[0], b1 = r4[1];
                B[0]=b0.x; B[1]=b0.y; B[2]=b0.z; B[3]=b0.w;
                B[4]=b1.x; B[5]=b1.y; B[6]=b1.z; B[7]=b1.w;
            }
            if (row > 0) {
                const float4* r4 = (const float4*)(rr + (row - 1) * 8);
                float4 a0 = r4[0], a1 = r4[1];
                A[0]=a0.x; A[1]=a0.y; A[2]=a0.z; A[3]=a0.w;
                A[4]=a1.x; A[5]=a1.y; A[6]=a1.z; A[7]=a1.w;
            } else {
#pragma unroll
                for (int j = 0; j < 8; j++) A[j] = 0.f;
            }
            if (row < 7) {
                const float4* r4 = (const float4*)(rr + (row + 1) * 8);
                float4 c0 = r4[0], c1 = r4[1];
                C[0]=c0.x; C[1]=c0.y; C[2]=c0.z; C[3]=c0.w;
                C[4]=c1.x; C[5]=c1.y; C[6]=c1.z; C[7]=c1.w;
            } else {
#pragma unroll
                for (int j = 0; j < 8; j++) C[j] = 0.f;
            }
            float o[8];
            float ss = 0.f;
#pragma unroll
            for (int j = 0; j < 8; j++) {
                float s = w1 * A[j] + w4 * B[j] + w7 * C[j];
                if (j > 0) s += w0 * A[j-1] + w3 * B[j-1] + w6 * C[j-1];
                if (j < 7) s += w2 * A[j+1] + w5 * B[j+1] + w8 * C[j+1];
                o[j] = s;
                ss += s * s;
            }
            ss += __shfl_xor_sync(0xffffffffu, ss, 4);
            ss += __shfl_xor_sync(0xffffffffu, ss, 2);
            ss += __shfl_xor_sync(0xffffffffu, ss, 1);
            __syncwarp();
            float4* w4p = (float4*)(rr + row * 8);
            w4p[0] = make_float4(__uint_as_float(f2tf32(o[0])), __uint_as_float(f2tf32(o[1])),
                                 __uint_as_float(f2tf32(o[2])), __uint_as_float(f2tf32(o[3])));
            w4p[1] = make_float4(__uint_as_float(f2tf32(o[4])), __uint_as_float(f2tf32(o[5])),
                                 __uint_as_float(f2tf32(o[6])), __uint_as_float(f2tf32(o[7])));
            if ((lane & 7) == 0)
                Ns[ch_] = 1.f / fmaxf(sqrtf(ss), 1e-12f);
            __syncwarp();
        }
        // V -> transposed Vt in Ra (tf32)
#pragma unroll
        for (int it = 0; it < 3; it++) {
            int task = it * NTHR + tid;
            int ch = task % DIM;
            int row = task / DIM;
            const float* rr = Rd + ch * STRC;
            const float* wd = dw_w + (size_t)(2 * DIM + ch) * 9;
            float w0 = __ldg(wd+0), w1 = __ldg(wd+1), w2 = __ldg(wd+2);
            float w3 = __ldg(wd+3), w4 = __ldg(wd+4), w5 = __ldg(wd+5);
            float w6 = __ldg(wd+6), w7 = __ldg(wd+7), w8 = __ldg(wd+8);
            float A[8], B[8], C[8];
            {
                const float4* r4 = (const float4*)(rr + row * 8);
                float4 b0 = r4[0], b1 = r4[1];
                B[0]=b0.x; B[1]=b0.y; B[2]=b0.z; B[3]=b0.w;
                B[4]=b1.x; B[5]=b1.y; B[6]=b1.z; B[7]=b1.w;
            }
            if (row > 0) {
                const float4* r4 = (const float4*)(rr + (row - 1) * 8);
                float4 a0 = r4[0], a1 = r4[1];
                A[0]=a0.x; A[1]=a0.y; A[2]=a0.z; A[3]=a0.w;
                A[4]=a1.x; A[5]=a1.y; A[6]=a1.z; A[7]=a1.w;
            } else {
#pragma unroll
                for (int j = 0; j < 8; j++) A[j] = 0.f;
            }
            if (row < 7) {
                const float4* r4 = (const float4*)(rr + (row + 1) * 8);
                float4 c0 = r4[0], c1 = r4[1];
                C[0]=c0.x; C[1]=c0.y; C[2]=c0.z; C[3]=c0.w;
                C[4]=c1.x; C[5]=c1.y; C[6]=c1.z; C[7]=c1.w;
            } else {
#pragma unroll
                for (int j = 0; j < 8; j++) C[j] = 0.f;
            }
#pragma unroll
            for (int j = 0; j < 8; j++) {
                float s = w1 * A[j] + w4 * B[j] + w7 * C[j];
                if (j > 0) s += w0 * A[j-1] + w3 * B[j-1] + w6 * C[j-1];
                if (j < 7) s += w2 * A[j+1] + w5 * B[j+1] + w8 * C[j+1];
                Ra[(row * 8 + j) * STRK + ch] = __uint_as_float(f2tf32(s));
            }
        }
    }
    __syncthreads();

    // ---- scores via mma.sync: S = q @ k^T per head -> As (Rd) ----
    {
        const uint32_t* Qu = (const uint32_t*)Rb;
        const uint32_t* Ku = (const uint32_t*)Rc;
        float* As = Rd;
        const int gid = lane >> 2, tig = lane & 3;
#pragma unroll
        for (int i = 0; i < 3; i++) {
            int t = wid + 16 * i;
            int head = t >> 3, mt = (t >> 2) & 1, nt = t & 3;
            int bm = head * 32 + mt * 16, bn = head * 32 + nt * 8;
            float dacc[4] = {0.f, 0.f, 0.f, 0.f};
#pragma unroll
            for (int kc = 0; kc < 8; kc++) {
                int kk = kc * 8;
                uint32_t areg[4], breg[2];
                areg[0] = Qu[(bm + gid) * STRC + kk + tig];
                areg[1] = Qu[(bm + gid + 8) * STRC + kk + tig];
                areg[2] = Qu[(bm + gid) * STRC + kk + tig + 4];
                areg[3] = Qu[(bm + gid + 8) * STRC + kk + tig + 4];
                breg[0] = Ku[(bn + gid) * STRC + kk + tig];
                breg[1] = Ku[(bn + gid) * STRC + kk + tig + 4];
                mma16n8k8(dacc, areg, breg);
            }
            float tmp = __ldg(temperature + head);
            float iq0 = Ns[bm + gid] * tmp, iq8 = Ns[bm + gid + 8] * tmp;
            float ik0 = Ns[DIM + bn + 2 * tig], ik1 = Ns[DIM + bn + 2 * tig + 1];
            int dn = nt * 8 + 2 * tig;
            As[(bm + gid) * STRA + dn]         = dacc[0] * iq0 * ik0;
            As[(bm + gid) * STRA + dn + 1]     = dacc[1] * iq0 * ik1;
            As[(bm + gid + 8) * STRA + dn]     = dacc[2] * iq8 * ik0;
            As[(bm + gid + 8) * STRA + dn + 1] = dacc[3] * iq8 * ik1;
        }
    }
    __syncthreads();

    // ---- softmax over d (rows of As, stride 33); store tf32-rounded ----
    if (tid < DIM) {
        float* arow = Rd + tid * STRA;
        float m = arow[0];
#pragma unroll
        for (int d = 1; d < 32; d++) m = fmaxf(m, arow[d]);
        float s = 0.f;
        float ev[32];
#pragma unroll
        for (int d = 0; d < 32; d++) { ev[d] = expf(arow[d] - m); s += ev[d]; }
        float inv = 1.f / s;
#pragma unroll
        for (int d = 0; d < 32; d++) arow[d] = __uint_as_float(f2tf32(ev[d] * inv));
    }
    __syncthreads();

    // ---- attn@v via mma.sync: O = A @ V -> Rb tf32 [192][68] ----
    {
        const uint32_t* Au = (const uint32_t*)Rd;
        const uint32_t* Vu = (const uint32_t*)Ra;
        uint32_t* Ou = (uint32_t*)Rb;
        const int gid = lane >> 2, tig = lane & 3;
#pragma unroll
        for (int i = 0; i < 6; i++) {
            int t = wid + 16 * i;
            int head = t >> 4, mt = (t >> 3) & 1, nt = t & 7;
            int bm = head * 32 + mt * 16, bn = nt * 8;
            float dacc[4] = {0.f, 0.f, 0.f, 0.f};
#pragma unroll
            for (int kc = 0; kc < 4; kc++) {
                int kk = kc * 8;
                uint32_t areg[4], breg[2];
                areg[0] = Au[(bm + gid) * STRA + kk + tig];
                areg[1] = Au[(bm + gid + 8) * STRA + kk + tig];
                areg[2] = Au[(bm + gid) * STRA + kk + tig + 4];
                areg[3] = Au[(bm + gid + 8) * STRA + kk + tig + 4];
                breg[0] = Vu[(bn + gid) * STRK + head * 32 + kk + tig];
                breg[1] = Vu[(bn + gid) * STRK + head * 32 + kk + tig + 4];
                mma16n8k8(dacc, areg, breg);
            }
            Ou[(bm + gid) * STRC + bn + 2 * tig]         = f2tf32(dacc[0]);
            Ou[(bm + gid) * STRC + bn + 2 * tig + 1]     = f2tf32(dacc[1]);
            Ou[(bm + gid + 8) * STRC + bn + 2 * tig]     = f2tf32(dacc[2]);
            Ou[(bm + gid + 8) * STRC + bn + 2 * tig + 1] = f2tf32(dacc[3]);
        }
    }
    __syncthreads();

    // ---- proj GEMM via mma.sync tf32, weights staged in Ra (16-k chunks) ----
    {
        const uint32_t* Xu = (const uint32_t*)Rb;
        const int gid = lane >> 2, tig = lane & 3;
        const int mgr = wid >> 2, ngr = wid & 3;
        float dacc[3][2][4];
#pragma unroll
        for (int mt = 0; mt < 3; mt++)
#pragma unroll
            for (int nt = 0; nt < 2; nt++)
#pragma unroll
                for (int q = 0; q < 4; q++) dacc[mt][nt][q] = 0.f;

        {
            const uint4* src = (const uint4*)g_projK;
            for (int e = tid; e < 768; e += NTHR) {
                int r = e / 48, c4 = e - r * 48;
                ((uint4*)((uint32_t*)Ra + r * PSTR))[c4] = __ldg(src + e);
            }
        }
        __syncthreads();

        for (int kc = 0; kc < 12; kc++) {
            const uint32_t* Wc = (const uint32_t*)Ra + (kc & 1) * 3200;
            if (kc < 11) {
                uint32_t* Wn = (uint32_t*)Ra + ((kc + 1) & 1) * 3200;
                const uint4* src = (const uint4*)(g_projK + (size_t)(kc + 1) * 16 * DIM);
                for (int e = tid; e < 768; e += NTHR) {
                    int r = e / 48, c4 = e - r * 48;
                    ((uint4*)(Wn + r * PSTR))[c4] = __ldg(src + e);
                }
            }
#pragma unroll
            for (int ks = 0; ks < 2; ks++) {
                const int kk = ks * 8;
                uint32_t breg[2][2];
#pragma unroll
                for (int nt = 0; nt < 2; nt++) {
                    int col = ngr * 16 + nt * 8 + gid;
                    breg[nt][0] = Xu[(kc * 16 + kk + tig) * STRC + col];
                    breg[nt][1] = Xu[(kc * 16 + kk + tig + 4) * STRC + col];
                }
#pragma unroll
                for (int mt = 0; mt < 3; mt++) {
                    int mcol = mgr * 48 + mt * 16 + gid;
                    uint32_t areg[4];
                    areg[0] = Wc[(kk + tig) * PSTR + mcol];
                    areg[1] = Wc[(kk + tig) * PSTR + mcol + 8];
                    areg[2] = Wc[(kk + tig + 4) * PSTR + mcol];
                    areg[3] = Wc[(kk + tig + 4) * PSTR + mcol + 8];
#pragma unroll
                    for (int nt = 0; nt < 2; nt++)
                        mma16n8k8(dacc[mt][nt], areg, breg[nt]);
                }
            }
            __syncthreads();
        }

        // epilogue: fragments -> gmem with roll(+4,+4)
#pragma unroll
        for (int mt = 0; mt < 3; mt++) {
#pragma unroll
            for (int half = 0; half < 2; half++) {
                int o = mgr * 48 + mt * 16 + gid + half * 8;
                float* obase = out + ((size_t)(bi * DIM + o) * IMG) * IMG;
#pragma unroll
                for (int nt = 0; nt < 2; nt++) {
                    int p = ngr * 16 + nt * 8 + 2 * tig;
                    int i = p >> 3, j = p & 7;
                    int gh = (wh * WSZ + i + SHIFTV) & 255;
                    int gw0 = (ww * WSZ + j + SHIFTV) & 255;
                    int gw1 = (ww * WSZ + j + 1 + SHIFTV) & 255;
                    obase[gh * IMG + gw0] = dacc[mt][nt][half * 2];
                    obase[gh * IMG + gw1] = dacc[mt][nt][half * 2 + 1];
                }
            }
        }
    }
}

extern "C" void kernel_launch(void* const* d_in, const int* in_sizes, int n_in,
                              void* d_out, int out_size) {
    const float* x           = (const float*)d_in[0];
    const float* qkv_w       = (const float*)d_in[1];
    const float* dw_w        = (const float*)d_in[2];
    const float* proj_w      = (const float*)d_in[3];
    const float* temperature = (const float*)d_in[4];
    float* out = (float*)d_out;

    cudaFuncSetAttribute(attn_kernel, cudaFuncAttributeMaxDynamicSharedMemorySize,
                         SMEM_FLOATS * 4);
    wtrans_kernel<<<(DIM * 640 + 255) / 256, 256>>>(qkv_w, proj_w);
    attn_kernel<<<4096, NTHR, SMEM_FLOATS * 4>>>(x, dw_w, temperature, out);
}